// round 3
// baseline (speedup 1.0000x reference)
#include <cuda_runtime.h>

#define KQ     12
#define D_NBR  320
#define D_NEW  256
#define HQ     8
#define DKQ    32
#define A_CTA  2
#define THREADS 128
#define LN_EPS 1e-5f

typedef unsigned long long u64;

__device__ __forceinline__ u64 pack2(float f) {
    u64 d; asm("mov.b64 %0, {%1, %1};" : "=l"(d) : "f"(f)); return d;
}
__device__ __forceinline__ u64 ffma2(u64 a, u64 b, u64 c) {
    u64 d; asm("fma.rn.f32x2 %0, %1, %2, %3;" : "=l"(d) : "l"(a), "l"(b), "l"(c)); return d;
}
__device__ __forceinline__ u64 fadd2(u64 a, u64 b) {
    u64 d; asm("add.rn.f32x2 %0, %1, %2;" : "=l"(d) : "l"(a), "l"(b)); return d;
}

// Dynamic smem layout (bytes):
//   s_dup  : A_CTA*12*320 u64  = 61440   duplicated nbr {f,f}; later overlaid by e (fp32, 24KB)
//   s_adup : A_CTA*256  u64    =  4096   duplicated atom
//   s_h    : A_CTA*256  f32    =  2048
#define DUP_ELEMS  (A_CTA * KQ * D_NBR)
#define ADUP_ELEMS (A_CTA * 256)
#define DYN_BYTES  (DUP_ELEMS * 8 + ADUP_ELEMS * 8 + A_CTA * 256 * 4)

__global__ void __launch_bounds__(THREADS, 3)
gnn_fused3(const float* __restrict__ atom,    // (B*N, 256)
           const float* __restrict__ nbr,     // (B*N, 12, 320)
           const float* __restrict__ smask,   // (B*N, 12)
           const float* __restrict__ amask,   // (B*N, 12)
           const float* __restrict__ Wa,      // (256, 256)
           const float* __restrict__ ba,      // (256,)
           const float* __restrict__ Wn,      // (320, 256)
           const float* __restrict__ bnb,     // (256,)
           const float* __restrict__ wal,     // (32,)
           const float* __restrict__ bal,     // (1,)
           const float* __restrict__ gamma,   // (256,)
           const float* __restrict__ beta,    // (256,)
           float* __restrict__ out)           // (B*N, 256)
{
    extern __shared__ char dyn[];
    u64*   s_dup  = (u64*)dyn;                          // duplicated nbr
    u64*   s_adup = s_dup + DUP_ELEMS;                  // duplicated atom
    float* s_h    = (float*)(s_adup + ADUP_ELEMS);
    float* s_e    = (float*)dyn;                        // e overlays s_dup after sync

    __shared__ float s_score[A_CTA][KQ][HQ];
    __shared__ float s_attn[A_CTA][KQ][HQ];
    __shared__ float s_smask[A_CTA * KQ];
    __shared__ float s_amask[A_CTA * KQ];
    __shared__ float s_wal[DKQ];
    __shared__ float s_bal;
    __shared__ float s_red[4][2];
    __shared__ float s_stat[A_CTA][2];

    const int t   = threadIdx.x;
    const int g   = t >> 6;
    const int tx  = t & 63;
    const int bn0 = blockIdx.x * A_CTA;

    // ---------------- stage (duplicate-on-write) ----------------
    {
        const float4* src = (const float4*)(nbr + (size_t)bn0 * (KQ * D_NBR));
        #pragma unroll
        for (int i = 0; i < DUP_ELEMS / 4 / THREADS; ++i) {   // 15
            const int idx = t + i * THREADS;
            float4 v = src[idx];
            ulonglong2* d = (ulonglong2*)&s_dup[idx * 4];
            ulonglong2 p0, p1;
            p0.x = pack2(v.x); p0.y = pack2(v.y);
            p1.x = pack2(v.z); p1.y = pack2(v.w);
            d[0] = p0; d[1] = p1;
        }
        float4 av = ((const float4*)(atom + (size_t)bn0 * 256))[t];
        ulonglong2* da = (ulonglong2*)&s_adup[t * 4];
        ulonglong2 q0, q1;
        q0.x = pack2(av.x); q0.y = pack2(av.y);
        q1.x = pack2(av.z); q1.y = pack2(av.w);
        da[0] = q0; da[1] = q1;
        if (t < A_CTA * KQ) {
            s_smask[t] = smask[bn0 * KQ + t];
            s_amask[t] = amask[bn0 * KQ + t];
        }
        if (t < DKQ) s_wal[t] = wal[t];
        if (t == 64) s_bal = bal[0];
    }
    __syncthreads();

    // ---------------- e-GEMM: 12 rows x 4 cols, pure FFMA2 ----------------
    u64 acc[KQ][2];
    #pragma unroll
    for (int r = 0; r < KQ; ++r) { acc[r][0] = 0ull; acc[r][1] = 0ull; }

    const u64* nbd = s_dup + g * (KQ * D_NBR);
    #pragma unroll 2
    for (int c0 = 0; c0 < D_NBR; c0 += 4) {
        u64 wlo[4], whi[4];
        #pragma unroll
        for (int i = 0; i < 4; ++i) {
            ulonglong2 wv = *(const ulonglong2*)(Wn + (size_t)(c0 + i) * D_NEW + tx * 4);
            wlo[i] = wv.x; whi[i] = wv.y;
        }
        #pragma unroll
        for (int r = 0; r < KQ; ++r) {
            ulonglong2 p01 = *(const ulonglong2*)(nbd + r * D_NBR + c0);      // {f0,f0},{f1,f1}
            ulonglong2 p23 = *(const ulonglong2*)(nbd + r * D_NBR + c0 + 2);  // {f2,f2},{f3,f3}
            acc[r][0] = ffma2(p01.x, wlo[0], acc[r][0]); acc[r][1] = ffma2(p01.x, whi[0], acc[r][1]);
            acc[r][0] = ffma2(p01.y, wlo[1], acc[r][0]); acc[r][1] = ffma2(p01.y, whi[1], acc[r][1]);
            acc[r][0] = ffma2(p23.x, wlo[2], acc[r][0]); acc[r][1] = ffma2(p23.x, whi[2], acc[r][1]);
            acc[r][0] = ffma2(p23.y, wlo[3], acc[r][0]); acc[r][1] = ffma2(p23.y, whi[3], acc[r][1]);
        }
    }

    // ---------------- h-GEMM ----------------
    u64 h0 = 0ull, h1 = 0ull;
    {
        const u64* ad = s_adup + g * 256;
        #pragma unroll 2
        for (int c0 = 0; c0 < 256; c0 += 4) {
            u64 wlo[4], whi[4];
            #pragma unroll
            for (int i = 0; i < 4; ++i) {
                ulonglong2 wv = *(const ulonglong2*)(Wa + (size_t)(c0 + i) * D_NEW + tx * 4);
                wlo[i] = wv.x; whi[i] = wv.y;
            }
            ulonglong2 a01 = *(const ulonglong2*)(ad + c0);
            ulonglong2 a23 = *(const ulonglong2*)(ad + c0 + 2);
            h0 = ffma2(a01.x, wlo[0], h0); h1 = ffma2(a01.x, whi[0], h1);
            h0 = ffma2(a01.y, wlo[1], h0); h1 = ffma2(a01.y, whi[1], h1);
            h0 = ffma2(a23.x, wlo[2], h0); h1 = ffma2(a23.x, whi[2], h1);
            h0 = ffma2(a23.y, wlo[3], h0); h1 = ffma2(a23.y, whi[3], h1);
        }
    }

    __syncthreads();   // all dup reads done before e overlays s_dup

    // ---------------- write e (+bias) and h (+bias) ----------------
    {
        ulonglong2 bv = *(const ulonglong2*)(bnb + tx * 4);
        #pragma unroll
        for (int r = 0; r < KQ; ++r) {
            u64* p = (u64*)(s_e + (g * KQ + r) * D_NEW + tx * 4);
            p[0] = fadd2(acc[r][0], bv.x);
            p[1] = fadd2(acc[r][1], bv.y);
        }
        ulonglong2 bav = *(const ulonglong2*)(ba + tx * 4);
        u64* ph = (u64*)(s_h + g * 256 + tx * 4);
        ph[0] = fadd2(h0, bav.x);
        ph[1] = fadd2(h1, bav.y);
    }
    __syncthreads();

    // ---------------- GATv2 scores ----------------
    const float bal0 = s_bal;
    for (int idx = t; idx < A_CTA * KQ * HQ; idx += THREADS) {   // 192 tasks
        const int gg  = idx / (KQ * HQ);
        const int rem = idx - gg * (KQ * HQ);
        const int k   = rem >> 3;
        const int hh  = rem & 7;
        const float* hv = s_h + gg * 256 + hh * DKQ;
        const float* ev = s_e + (gg * KQ + k) * D_NEW + hh * DKQ;
        float sc = 0.f;
        #pragma unroll
        for (int i = 0; i < DKQ; ++i) {
            float x = hv[i] + ev[i];
            x = fmaxf(x, 0.01f * x);
            sc = fmaf(x, s_wal[i], sc);
        }
        s_score[gg][k][hh] = sc + bal0 + s_smask[gg * KQ + k];
    }
    __syncthreads();

    // ---------------- softmax over K per (atom, head) ----------------
    if (t < A_CTA * HQ) {
        const int gg = t >> 3, hh = t & 7;
        float mx = -3.4e38f;
        #pragma unroll
        for (int k = 0; k < KQ; ++k) mx = fmaxf(mx, s_score[gg][k][hh]);
        float ex[KQ], sum = 0.f;
        #pragma unroll
        for (int k = 0; k < KQ; ++k) { ex[k] = __expf(s_score[gg][k][hh] - mx); sum += ex[k]; }
        const float inv = 1.f / sum;
        #pragma unroll
        for (int k = 0; k < KQ; ++k) s_attn[gg][k][hh] = ex[k] * inv * s_amask[gg * KQ + k];
    }
    __syncthreads();

    // ---------------- ctx + LayerNorm ----------------
    const int hh = tx >> 3;
    float c0 = 0.f, c1 = 0.f, c2 = 0.f, c3 = 0.f;
    #pragma unroll
    for (int k = 0; k < KQ; ++k) {
        const float a = s_attn[g][k][hh];
        const float4 ev = *(const float4*)(s_e + (g * KQ + k) * D_NEW + tx * 4);
        c0 = fmaf(a, ev.x, c0);
        c1 = fmaf(a, ev.y, c1);
        c2 = fmaf(a, ev.z, c2);
        c3 = fmaf(a, ev.w, c3);
    }
    float v  = c0 + c1 + c2 + c3;
    float v2 = c0 * c0 + c1 * c1 + c2 * c2 + c3 * c3;
    #pragma unroll
    for (int o = 16; o > 0; o >>= 1) {
        v  += __shfl_xor_sync(0xffffffffu, v, o);
        v2 += __shfl_xor_sync(0xffffffffu, v2, o);
    }
    const int warp = t >> 5, lane = t & 31;
    if (lane == 0) { s_red[warp][0] = v; s_red[warp][1] = v2; }
    __syncthreads();
    if (t < A_CTA) {
        const float s  = s_red[2 * t][0] + s_red[2 * t + 1][0];
        const float s2 = s_red[2 * t][1] + s_red[2 * t + 1][1];
        const float mu  = s * (1.f / D_NEW);
        const float var = s2 * (1.f / D_NEW) - mu * mu;
        s_stat[t][0] = mu;
        s_stat[t][1] = rsqrtf(var + LN_EPS);
    }
    __syncthreads();
    const float mu  = s_stat[g][0];
    const float inv = s_stat[g][1];
    const float4 gv = *(const float4*)(gamma + tx * 4);
    const float4 bv = *(const float4*)(beta + tx * 4);
    float4 o;
    o.x = (c0 - mu) * inv * gv.x + bv.x;
    o.y = (c1 - mu) * inv * gv.y + bv.y;
    o.z = (c2 - mu) * inv * gv.z + bv.z;
    o.w = (c3 - mu) * inv * gv.w + bv.w;
    *(float4*)(out + (size_t)(bn0 + g) * D_NEW + tx * 4) = o;
}

extern "C" void kernel_launch(void* const* d_in, const int* in_sizes, int n_in,
                              void* d_out, int out_size)
{
    (void)in_sizes; (void)n_in; (void)out_size;
    const float* atom   = (const float*)d_in[0];
    const float* nbr    = (const float*)d_in[1];
    const float* smask  = (const float*)d_in[2];
    const float* amask  = (const float*)d_in[3];
    const float* Wa     = (const float*)d_in[4];
    const float* ba     = (const float*)d_in[5];
    const float* Wn     = (const float*)d_in[6];
    const float* bnb    = (const float*)d_in[7];
    const float* wal    = (const float*)d_in[8];
    const float* bal    = (const float*)d_in[9];
    const float* gamma  = (const float*)d_in[10];
    const float* beta   = (const float*)d_in[11];
    float* out = (float*)d_out;

    static int smem_set = 0;
    cudaFuncSetAttribute(gnn_fused3, cudaFuncAttributeMaxDynamicSharedMemorySize, DYN_BYTES);
    (void)smem_set;

    gnn_fused3<<<(64 * 128) / A_CTA, THREADS, DYN_BYTES>>>(atom, nbr, smask, amask,
                                                           Wa, ba, Wn, bnb, wal, bal,
                                                           gamma, beta, out);
}

// round 6
// speedup vs baseline: 1.8365x; 1.8365x over previous
#include <cuda_runtime.h>
#include <cuda_bf16.h>
#include <cstdint>

#define KQ     12
#define D_NBR  320
#define D_NEW  256
#define HQ     8
#define DKQ    32
#define LN_EPS 1e-5f
#define BN_TOT (64 * 128)          // 8192 atoms
#define M_E    (BN_TOT * KQ)       // 98304 neighbor rows
#define NC_E   (D_NBR / 32)        // 10 k-chunks (BK=32)
#define NC_H   (D_NEW / 32)        // 8 k-chunks
#define BLK_BYTES 16384            // one (128n x 32k) hi+lo image block (8KB + 8KB)

// ------------------------- device scratch -------------------------
__device__ __align__(16) unsigned char g_WnImg[2 * NC_E * BLK_BYTES];
__device__ __align__(16) unsigned char g_WaImg[2 * NC_H * BLK_BYTES];
__device__ float g_e[(size_t)M_E * 256];
__device__ float g_h[(size_t)BN_TOT * 256];

// ------------------------- helpers -------------------------
__device__ __forceinline__ uint32_t smem_u32(const void* p) {
    uint32_t a;
    asm("{ .reg .u64 t; cvta.to.shared.u64 t, %1; cvt.u32.u64 %0, t; }" : "=r"(a) : "l"(p));
    return a;
}
__device__ __forceinline__ void ldmx4(uint32_t* r, uint32_t addr) {
    asm volatile("ldmatrix.sync.aligned.m8n8.x4.shared.b16 {%0,%1,%2,%3}, [%4];"
        : "=r"(r[0]), "=r"(r[1]), "=r"(r[2]), "=r"(r[3]) : "r"(addr));
}
__device__ __forceinline__ void mma_bf16(float* d, const uint32_t* a, const uint32_t* b) {
    asm volatile(
        "mma.sync.aligned.m16n8k16.row.col.f32.bf16.bf16.f32 "
        "{%0,%1,%2,%3}, {%4,%5,%6,%7}, {%8,%9}, {%0,%1,%2,%3};"
        : "+f"(d[0]), "+f"(d[1]), "+f"(d[2]), "+f"(d[3])
        : "r"(a[0]), "r"(a[1]), "r"(a[2]), "r"(a[3]), "r"(b[0]), "r"(b[1]));
}
__device__ __forceinline__ void cp16(uint32_t saddr, const void* g) {
    asm volatile("cp.async.cg.shared.global [%0], [%1], 16;" :: "r"(saddr), "l"(g) : "memory");
}
#define CP_COMMIT() asm volatile("cp.async.commit_group;" ::: "memory")
#define CP_WAIT(n)  asm volatile("cp.async.wait_group %0;" :: "n"(n) : "memory")

// swizzled offset inside one 128x32 bf16 image (row-major rows of 64B)
__device__ __host__ __forceinline__ uint32_t swz(int r, int k) {
    return (uint32_t)(r * 64 + ((((k >> 3) ^ ((r >> 1) & 3))) << 4) + (k & 7) * 2);
}
__device__ __forceinline__ uint32_t pack_bf2(float a, float b) {
    __nv_bfloat162 p = __floats2bfloat162_rn(a, b);
    return *(uint32_t*)&p;
}

// ------------------------- prep: split W into bf16 hi/lo swizzled images -------------------------
__global__ void prep_w(const float* __restrict__ Wn, const float* __restrict__ Wa) {
    int i = blockIdx.x * blockDim.x + threadIdx.x;
    const float* W; unsigned char* img; int NC, idx;
    if (i < D_NBR * 256)                    { W = Wn; img = g_WnImg; NC = NC_E; idx = i; }
    else if (i < (D_NBR + D_NEW) * 256)     { W = Wa; img = g_WaImg; NC = NC_H; idx = i - D_NBR * 256; }
    else return;
    const int k = idx >> 8, n = idx & 255;
    const int ntile = n >> 7, nl = n & 127, kc = k >> 5, kl = k & 31;
    const float x = W[k * 256 + n];
    const __nv_bfloat16 hi = __float2bfloat16(x);
    const __nv_bfloat16 lo = __float2bfloat16(x - __bfloat162float(hi));
    unsigned char* base = img + (size_t)(ntile * NC + kc) * BLK_BYTES;
    const uint32_t off = swz(nl, kl);
    *(__nv_bfloat16*)(base + off)        = hi;
    *(__nv_bfloat16*)(base + 8192 + off) = lo;
}

// ------------------------- bf16x3 mma GEMM: out[M,256] = X[M,K] @ W[K,256] + bias -----------------
// grid = (M/128, 2); block = 256 (8 warps, warp tile 32m x 64n); BK = 32, double-buffered.
// Two-sync pipeline: sync1 (top) protects write-after-read on stage st^1 before cp.async/STS issue;
// sync2 (after CP_WAIT) makes stage st visible before ldmatrix.
__global__ void __launch_bounds__(256, 1)
gemm_mma(const float* __restrict__ X, const float* __restrict__ bias, int K, int NC, int which)
{
    extern __shared__ unsigned char sm[];
    const unsigned char* img = which ? g_WaImg : g_WnImg;
    float* out = which ? g_h : g_e;

    const int t = threadIdx.x;
    const int lane = t & 31, wid = t >> 5;
    const int m0 = blockIdx.x * 128;
    const int nblk = blockIdx.y;

    const uint32_t sA = smem_u32(sm);          // 2 stages x (hi 8KB + lo 8KB)
    const uint32_t sB = sA + 32768;            // same

    const int wm = (wid & 3) * 32;
    const int wn = (wid >> 2) * 64;

    const int laneMA  = (lane & 7) + ((lane >> 3) & 1) * 8;   // A: +8 rows on tile bit0
    const int laneK8A = lane >> 4;                            // A: +8 k on tile bit1
    const int laneNB  = (lane & 7) + ((lane >> 4) & 1) * 8;   // B: +8 n on tile bit1
    const int laneK8B = (lane >> 3) & 1;                      // B: +8 k on tile bit0

    int mA[2]; mA[0] = wm + laneMA; mA[1] = wm + 16 + laneMA;
    int nB[4];
    #pragma unroll
    for (int nt = 0; nt < 4; ++nt) nB[nt] = wn + nt * 16 + laneNB;

    float acc[2][8][4];
    #pragma unroll
    for (int mt = 0; mt < 2; ++mt)
        #pragma unroll
        for (int ng = 0; ng < 8; ++ng)
            #pragma unroll
            for (int j = 0; j < 4; ++j) acc[mt][ng][j] = 0.f;

    // ---- staging identities ----
    const int srow = t >> 1, shalf = t & 1;                   // A: row, k-half (16 elems)
    const float* Xrow = X + (size_t)(m0 + srow) * K + shalf * 16;
    const uint32_t offH0 = swz(srow, shalf * 16);
    const uint32_t offH1 = swz(srow, shalf * 16 + 8);

    float4 pf[4];
    #define LDA(kc) do { \
        const float4* xp = (const float4*)(Xrow + (kc) * 32); \
        pf[0] = xp[0]; pf[1] = xp[1]; pf[2] = xp[2]; pf[3] = xp[3]; } while (0)

    #define CVTSTS(st) do { \
        uint32_t ab = sA + (st) * 16384; \
        uint4 hi0, lo0, hi1, lo1; \
        hi0.x = pack_bf2(pf[0].x, pf[0].y); hi0.y = pack_bf2(pf[0].z, pf[0].w); \
        hi0.z = pack_bf2(pf[1].x, pf[1].y); hi0.w = pack_bf2(pf[1].z, pf[1].w); \
        hi1.x = pack_bf2(pf[2].x, pf[2].y); hi1.y = pack_bf2(pf[2].z, pf[2].w); \
        hi1.z = pack_bf2(pf[3].x, pf[3].y); hi1.w = pack_bf2(pf[3].z, pf[3].w); \
        lo0.x = pack_bf2(pf[0].x - __bfloat162float(__float2bfloat16(pf[0].x)), \
                         pf[0].y - __bfloat162float(__float2bfloat16(pf[0].y))); \
        lo0.y = pack_bf2(pf[0].z - __bfloat162float(__float2bfloat16(pf[0].z)), \
                         pf[0].w - __bfloat162float(__float2bfloat16(pf[0].w))); \
        lo0.z = pack_bf2(pf[1].x - __bfloat162float(__float2bfloat16(pf[1].x)), \
                         pf[1].y - __bfloat162float(__float2bfloat16(pf[1].y))); \
        lo0.w = pack_bf2(pf[1].z - __bfloat162float(__float2bfloat16(pf[1].z)), \
                         pf[1].w - __bfloat162float(__float2bfloat16(pf[1].w))); \
        lo1.x = pack_bf2(pf[2].x - __bfloat162float(__float2bfloat16(pf[2].x)), \
                         pf[2].y - __bfloat162float(__float2bfloat16(pf[2].y))); \
        lo1.y = pack_bf2(pf[2].z - __bfloat162float(__float2bfloat16(pf[2].z)), \
                         pf[2].w - __bfloat162float(__float2bfloat16(pf[2].w))); \
        lo1.z = pack_bf2(pf[3].x - __bfloat162float(__float2bfloat16(pf[3].x)), \
                         pf[3].y - __bfloat162float(__float2bfloat16(pf[3].y))); \
        lo1.w = pack_bf2(pf[3].z - __bfloat162float(__float2bfloat16(pf[3].z)), \
                         pf[3].w - __bfloat162float(__float2bfloat16(pf[3].w))); \
        asm volatile("st.shared.v4.b32 [%0], {%1,%2,%3,%4};" :: "r"(ab + offH0), \
            "r"(hi0.x), "r"(hi0.y), "r"(hi0.z), "r"(hi0.w) : "memory"); \
        asm volatile("st.shared.v4.b32 [%0], {%1,%2,%3,%4};" :: "r"(ab + offH1), \
            "r"(hi1.x), "r"(hi1.y), "r"(hi1.z), "r"(hi1.w) : "memory"); \
        asm volatile("st.shared.v4.b32 [%0], {%1,%2,%3,%4};" :: "r"(ab + 8192 + offH0), \
            "r"(lo0.x), "r"(lo0.y), "r"(lo0.z), "r"(lo0.w) : "memory"); \
        asm volatile("st.shared.v4.b32 [%0], {%1,%2,%3,%4};" :: "r"(ab + 8192 + offH1), \
            "r"(lo1.x), "r"(lo1.y), "r"(lo1.z), "r"(lo1.w) : "memory"); } while (0)

    #define CPB(kc, st) do { \
        const unsigned char* gsrc = img + (size_t)(nblk * NC + (kc)) * BLK_BYTES + t * 16; \
        uint32_t sdst = sB + (st) * 16384 + t * 16; \
        cp16(sdst,          gsrc); \
        cp16(sdst + 4096,   gsrc + 4096); \
        cp16(sdst + 8192,   gsrc + 8192); \
        cp16(sdst + 12288,  gsrc + 12288); } while (0)

    // ---- prologue: stage 0 ----
    LDA(0);
    CPB(0, 0); CP_COMMIT();
    CVTSTS(0);

    for (int kc = 0; kc < NC; ++kc) {
        const int st = kc & 1;

        // sync1: all warps finished reading stage st^1 (iter kc-1) -> safe to overwrite it
        __syncthreads();
        if (kc + 1 < NC) {
            LDA(kc + 1);
            CPB(kc + 1, st ^ 1); CP_COMMIT();
            CP_WAIT(1);          // stage st B complete; stage st^1 B may be in flight
        } else {
            CP_WAIT(0);
        }
        // sync2: stage st (cp.async B + STS A) visible to all warps
        __syncthreads();

        const uint32_t aBase = sA + st * 16384;
        const uint32_t bBase = sB + st * 16384;
        #pragma unroll
        for (int ks = 0; ks < 2; ++ks) {
            uint32_t ah[2][4], al[2][4], bh[4][4], bl[4][4];
            #pragma unroll
            for (int mt = 0; mt < 2; ++mt) {
                const int m = mA[mt];
                const int k8 = ks * 2 + laneK8A;
                const uint32_t off = (uint32_t)(m * 64 + ((k8 ^ ((m >> 1) & 3)) << 4));
                ldmx4(ah[mt], aBase + off);
                ldmx4(al[mt], aBase + 8192 + off);
            }
            #pragma unroll
            for (int nt = 0; nt < 4; ++nt) {
                const int n = nB[nt];
                const int k8 = ks * 2 + laneK8B;
                const uint32_t off = (uint32_t)(n * 64 + ((k8 ^ ((n >> 1) & 3)) << 4));
                ldmx4(bh[nt], bBase + off);
                ldmx4(bl[nt], bBase + 8192 + off);
            }
            #pragma unroll
            for (int mt = 0; mt < 2; ++mt)
                #pragma unroll
                for (int ng = 0; ng < 8; ++ng) {
                    const uint32_t* pbh = &bh[ng >> 1][(ng & 1) * 2];
                    const uint32_t* pbl = &bl[ng >> 1][(ng & 1) * 2];
                    mma_bf16(acc[mt][ng], ah[mt], pbh);
                    mma_bf16(acc[mt][ng], ah[mt], pbl);
                    mma_bf16(acc[mt][ng], al[mt], pbh);
                }
        }
        // write next A stage; ordered after sync1 of this iter (all kc-1 readers done)
        if (kc + 1 < NC) CVTSTS(st ^ 1);
    }

    // ---- epilogue: accum + bias -> global ----
    const int n0 = nblk * 128;
    #pragma unroll
    for (int mt = 0; mt < 2; ++mt) {
        const int r0 = m0 + wm + mt * 16 + (lane >> 2);
        #pragma unroll
        for (int ng = 0; ng < 8; ++ng) {
            const int c = n0 + wn + ng * 8 + (lane & 3) * 2;
            const float b0 = bias[c], b1 = bias[c + 1];
            float2 v0 = { acc[mt][ng][0] + b0, acc[mt][ng][1] + b1 };
            float2 v1 = { acc[mt][ng][2] + b0, acc[mt][ng][3] + b1 };
            *(float2*)(out + (size_t)r0 * 256 + c)       = v0;
            *(float2*)(out + (size_t)(r0 + 8) * 256 + c) = v1;
        }
    }
    #undef LDA
    #undef CVTSTS
    #undef CPB
}

// ------------------------- attention + softmax + ctx + LayerNorm -------------------------
__global__ void __launch_bounds__(128)
attn_ln(const float* __restrict__ smask, const float* __restrict__ amask,
        const float* __restrict__ wal, const float* __restrict__ bal,
        const float* __restrict__ gamma, const float* __restrict__ beta,
        float* __restrict__ out)
{
    __shared__ float s_e[2 * KQ * D_NEW];
    __shared__ float s_h[2 * D_NEW];
    __shared__ float s_score[2][KQ][HQ];
    __shared__ float s_attn[2][KQ][HQ];
    __shared__ float s_smask[2 * KQ];
    __shared__ float s_amask[2 * KQ];
    __shared__ float s_wal[DKQ];
    __shared__ float s_bal;
    __shared__ float s_red[4][2];
    __shared__ float s_stat[2][2];

    const int t   = threadIdx.x;
    const int g   = t >> 6;
    const int tx  = t & 63;
    const int bn0 = blockIdx.x * 2;

    {
        const float4* es = (const float4*)(g_e + (size_t)bn0 * KQ * 256);
        float4* ed = (float4*)s_e;
        #pragma unroll
        for (int i = 0; i < 12; ++i) ed[t + i * 128] = es[t + i * 128];
        ((float4*)s_h)[t] = ((const float4*)(g_h + (size_t)bn0 * 256))[t];
        if (t < 2 * KQ) {
            s_smask[t] = smask[bn0 * KQ + t];
            s_amask[t] = amask[bn0 * KQ + t];
        }
        if (t < DKQ) s_wal[t] = wal[t];
        if (t == 64) s_bal = bal[0];
    }
    __syncthreads();

    const float bal0 = s_bal;
    for (int idx = t; idx < 2 * KQ * HQ; idx += 128) {
        const int gg  = idx / (KQ * HQ);
        const int rem = idx - gg * (KQ * HQ);
        const int k   = rem >> 3;
        const int hh  = rem & 7;
        const float* hv = s_h + gg * 256 + hh * DKQ;
        const float* ev = s_e + (gg * KQ + k) * D_NEW + hh * DKQ;
        float sc = 0.f;
        #pragma unroll
        for (int i = 0; i < DKQ; ++i) {
            float x = hv[i] + ev[i];
            x = fmaxf(x, 0.01f * x);
            sc = fmaf(x, s_wal[i], sc);
        }
        s_score[gg][k][hh] = sc + bal0 + s_smask[gg * KQ + k];
    }
    __syncthreads();

    if (t < 2 * HQ) {
        const int gg = t >> 3, hh = t & 7;
        float mx = -3.4e38f;
        #pragma unroll
        for (int k = 0; k < KQ; ++k) mx = fmaxf(mx, s_score[gg][k][hh]);
        float ex[KQ], sum = 0.f;
        #pragma unroll
        for (int k = 0; k < KQ; ++k) { ex[k] = __expf(s_score[gg][k][hh] - mx); sum += ex[k]; }
        const float inv = 1.f / sum;
        #pragma unroll
        for (int k = 0; k < KQ; ++k) s_attn[gg][k][hh] = ex[k] * inv * s_amask[gg * KQ + k];
    }
    __syncthreads();

    const int hh = tx >> 3;
    float c0 = 0.f, c1 = 0.f, c2 = 0.f, c3 = 0.f;
    #pragma unroll
    for (int k = 0; k < KQ; ++k) {
        const float a = s_attn[g][k][hh];
        const float4 ev = *(const float4*)(s_e + (g * KQ + k) * D_NEW + tx * 4);
        c0 = fmaf(a, ev.x, c0);
        c1 = fmaf(a, ev.y, c1);
        c2 = fmaf(a, ev.z, c2);
        c3 = fmaf(a, ev.w, c3);
    }
    float v  = c0 + c1 + c2 + c3;
    float v2 = c0 * c0 + c1 * c1 + c2 * c2 + c3 * c3;
    #pragma unroll
    for (int o = 16; o > 0; o >>= 1) {
        v  += __shfl_xor_sync(0xffffffffu, v, o);
        v2 += __shfl_xor_sync(0xffffffffu, v2, o);
    }
    const int warp = t >> 5, lane = t & 31;
    if (lane == 0) { s_red[warp][0] = v; s_red[warp][1] = v2; }
    __syncthreads();
    if (t < 2) {
        const float s  = s_red[2 * t][0] + s_red[2 * t + 1][0];
        const float s2 = s_red[2 * t][1] + s_red[2 * t + 1][1];
        const float mu  = s * (1.f / D_NEW);
        const float var = s2 * (1.f / D_NEW) - mu * mu;
        s_stat[t][0] = mu;
        s_stat[t][1] = rsqrtf(var + LN_EPS);
    }
    __syncthreads();
    const float mu  = s_stat[g][0];
    const float inv = s_stat[g][1];
    const float4 gv = *(const float4*)(gamma + tx * 4);
    const float4 bv = *(const float4*)(beta + tx * 4);
    float4 o;
    o.x = (c0 - mu) * inv * gv.x + bv.x;
    o.y = (c1 - mu) * inv * gv.y + bv.y;
    o.z = (c2 - mu) * inv * gv.z + bv.z;
    o.w = (c3 - mu) * inv * gv.w + bv.w;
    *(float4*)(out + (size_t)(bn0 + g) * D_NEW + tx * 4) = o;
}

// ------------------------- launch -------------------------
#define GEMM_DYN_BYTES 65536

extern "C" void kernel_launch(void* const* d_in, const int* in_sizes, int n_in,
                              void* d_out, int out_size)
{
    (void)in_sizes; (void)n_in; (void)out_size;
    const float* atom   = (const float*)d_in[0];
    const float* nbr    = (const float*)d_in[1];
    const float* smask  = (const float*)d_in[2];
    const float* amask  = (const float*)d_in[3];
    const float* Wa     = (const float*)d_in[4];
    const float* ba     = (const float*)d_in[5];
    const float* Wn     = (const float*)d_in[6];
    const float* bnb    = (const float*)d_in[7];
    const float* wal    = (const float*)d_in[8];
    const float* bal    = (const float*)d_in[9];
    const float* gamma  = (const float*)d_in[10];
    const float* beta   = (const float*)d_in[11];
    float* out = (float*)d_out;

    cudaFuncSetAttribute(gemm_mma, cudaFuncAttributeMaxDynamicSharedMemorySize, GEMM_DYN_BYTES);

    prep_w<<<((D_NBR + D_NEW) * 256 + 255) / 256, 256>>>(Wn, Wa);
    gemm_mma<<<dim3(M_E / 128, 2), 256, GEMM_DYN_BYTES>>>(nbr, bnb, D_NBR, NC_E, 0);
    gemm_mma<<<dim3(BN_TOT / 128, 2), 256, GEMM_DYN_BYTES>>>(atom, ba, D_NEW, NC_H, 1);
    attn_ln<<<BN_TOT / 2, 128>>>(smask, amask, wal, bal, gamma, beta, out);
}

// round 7
// speedup vs baseline: 2.1303x; 1.1600x over previous
#include <cuda_runtime.h>
#include <cuda_bf16.h>
#include <cstdint>

#define KQ     12
#define D_NBR  320
#define D_NEW  256
#define HQ     8
#define DKQ    32
#define LN_EPS 1e-5f
#define BN_TOT (64 * 128)          // 8192 atoms
#define M_E    (BN_TOT * KQ)       // 98304 neighbor rows
#define NC_E   (D_NBR / 32)        // 10 k-chunks (BK=32)
#define NC_H   (D_NEW / 32)        // 8 k-chunks
#define BLK_BYTES 16384            // one (128n x 32k) hi+lo image block (8KB + 8KB)

// ------------------------- device scratch -------------------------
__device__ __align__(16) unsigned char g_WnImg[2 * NC_E * BLK_BYTES];
__device__ __align__(16) unsigned char g_WaImg[2 * NC_H * BLK_BYTES];
__device__ float g_e[(size_t)M_E * 256];
__device__ float g_h[(size_t)BN_TOT * 256];

// ------------------------- helpers -------------------------
__device__ __forceinline__ uint32_t smem_u32(const void* p) {
    uint32_t a;
    asm("{ .reg .u64 t; cvta.to.shared.u64 t, %1; cvt.u32.u64 %0, t; }" : "=r"(a) : "l"(p));
    return a;
}
__device__ __forceinline__ void ldmx4(uint32_t* r, uint32_t addr) {
    asm volatile("ldmatrix.sync.aligned.m8n8.x4.shared.b16 {%0,%1,%2,%3}, [%4];"
        : "=r"(r[0]), "=r"(r[1]), "=r"(r[2]), "=r"(r[3]) : "r"(addr));
}
__device__ __forceinline__ void mma_bf16(float* d, const uint32_t* a, const uint32_t* b) {
    asm volatile(
        "mma.sync.aligned.m16n8k16.row.col.f32.bf16.bf16.f32 "
        "{%0,%1,%2,%3}, {%4,%5,%6,%7}, {%8,%9}, {%0,%1,%2,%3};"
        : "+f"(d[0]), "+f"(d[1]), "+f"(d[2]), "+f"(d[3])
        : "r"(a[0]), "r"(a[1]), "r"(a[2]), "r"(a[3]), "r"(b[0]), "r"(b[1]));
}
__device__ __forceinline__ void cp16(uint32_t saddr, const void* g) {
    asm volatile("cp.async.cg.shared.global [%0], [%1], 16;" :: "r"(saddr), "l"(g) : "memory");
}
#define CP_COMMIT() asm volatile("cp.async.commit_group;" ::: "memory")
#define CP_WAIT(n)  asm volatile("cp.async.wait_group %0;" :: "n"(n) : "memory")

// swizzled offset inside one 128x32 bf16 image (row-major rows of 64B)
__device__ __host__ __forceinline__ uint32_t swz(int r, int k) {
    return (uint32_t)(r * 64 + ((((k >> 3) ^ ((r >> 1) & 3))) << 4) + (k & 7) * 2);
}
__device__ __forceinline__ uint32_t pack_bf2(float a, float b) {
    __nv_bfloat162 p = __floats2bfloat162_rn(a, b);
    return *(uint32_t*)&p;
}

// ------------------------- prep: split W into bf16 hi/lo swizzled images -------------------------
__global__ void prep_w(const float* __restrict__ Wn, const float* __restrict__ Wa) {
    int i = blockIdx.x * blockDim.x + threadIdx.x;
    const float* W; unsigned char* img; int NC, idx;
    if (i < D_NBR * 256)                    { W = Wn; img = g_WnImg; NC = NC_E; idx = i; }
    else if (i < (D_NBR + D_NEW) * 256)     { W = Wa; img = g_WaImg; NC = NC_H; idx = i - D_NBR * 256; }
    else return;
    const int k = idx >> 8, n = idx & 255;
    const int ntile = n >> 7, nl = n & 127, kc = k >> 5, kl = k & 31;
    const float x = W[k * 256 + n];
    const __nv_bfloat16 hi = __float2bfloat16(x);
    const __nv_bfloat16 lo = __float2bfloat16(x - __bfloat162float(hi));
    unsigned char* base = img + (size_t)(ntile * NC + kc) * BLK_BYTES;
    const uint32_t off = swz(nl, kl);
    *(__nv_bfloat16*)(base + off)        = hi;
    *(__nv_bfloat16*)(base + 8192 + off) = lo;
}

// ------------------------- bf16x3 mma GEMM: out[M,256] = X[M,K] @ W[K,256] + bias -----------------
// grid = (M/128, 2); block = 256 (8 warps, warp tile 32m x 64n); BK = 32, double-buffered.
// 2 CTAs/SM target (128-reg cap): B fragments loaded per nt-group to keep pressure low.
__global__ void __launch_bounds__(256, 2)
gemm_mma(const float* __restrict__ X, const float* __restrict__ bias, int K, int NC, int which)
{
    extern __shared__ unsigned char sm[];
    const unsigned char* img = which ? g_WaImg : g_WnImg;
    float* out = which ? g_h : g_e;

    const int t = threadIdx.x;
    const int lane = t & 31, wid = t >> 5;
    const int m0 = blockIdx.x * 128;
    const int nblk = blockIdx.y;

    const uint32_t sA = smem_u32(sm);          // 2 stages x (hi 8KB + lo 8KB)
    const uint32_t sB = sA + 32768;            // same

    const int wm = (wid & 3) * 32;
    const int wn = (wid >> 2) * 64;

    const int laneMA  = (lane & 7) + ((lane >> 3) & 1) * 8;   // A: +8 rows on tile bit0
    const int laneK8A = lane >> 4;                            // A: +8 k on tile bit1
    const int laneNB  = (lane & 7) + ((lane >> 4) & 1) * 8;   // B: +8 n on tile bit1
    const int laneK8B = (lane >> 3) & 1;                      // B: +8 k on tile bit0

    float acc[2][8][4];
    #pragma unroll
    for (int mt = 0; mt < 2; ++mt)
        #pragma unroll
        for (int ng = 0; ng < 8; ++ng)
            #pragma unroll
            for (int j = 0; j < 4; ++j) acc[mt][ng][j] = 0.f;

    // ---- staging identities ----
    const int srow = t >> 1, shalf = t & 1;                   // A: row, k-half (16 elems)
    const float* Xrow = X + (size_t)(m0 + srow) * K + shalf * 16;
    const uint32_t offH0 = swz(srow, shalf * 16);
    const uint32_t offH1 = swz(srow, shalf * 16 + 8);

    float4 pf[4];
    #define LDA(kc) do { \
        const float4* xp = (const float4*)(Xrow + (kc) * 32); \
        pf[0] = xp[0]; pf[1] = xp[1]; pf[2] = xp[2]; pf[3] = xp[3]; } while (0)

    #define CVTSTS(st) do { \
        uint32_t ab = sA + (st) * 16384; \
        uint4 hi0, lo0, hi1, lo1; \
        hi0.x = pack_bf2(pf[0].x, pf[0].y); hi0.y = pack_bf2(pf[0].z, pf[0].w); \
        hi0.z = pack_bf2(pf[1].x, pf[1].y); hi0.w = pack_bf2(pf[1].z, pf[1].w); \
        hi1.x = pack_bf2(pf[2].x, pf[2].y); hi1.y = pack_bf2(pf[2].z, pf[2].w); \
        hi1.z = pack_bf2(pf[3].x, pf[3].y); hi1.w = pack_bf2(pf[3].z, pf[3].w); \
        lo0.x = pack_bf2(pf[0].x - __bfloat162float(__float2bfloat16(pf[0].x)), \
                         pf[0].y - __bfloat162float(__float2bfloat16(pf[0].y))); \
        lo0.y = pack_bf2(pf[0].z - __bfloat162float(__float2bfloat16(pf[0].z)), \
                         pf[0].w - __bfloat162float(__float2bfloat16(pf[0].w))); \
        lo0.z = pack_bf2(pf[1].x - __bfloat162float(__float2bfloat16(pf[1].x)), \
                         pf[1].y - __bfloat162float(__float2bfloat16(pf[1].y))); \
        lo0.w = pack_bf2(pf[1].z - __bfloat162float(__float2bfloat16(pf[1].z)), \
                         pf[1].w - __bfloat162float(__float2bfloat16(pf[1].w))); \
        lo1.x = pack_bf2(pf[2].x - __bfloat162float(__float2bfloat16(pf[2].x)), \
                         pf[2].y - __bfloat162float(__float2bfloat16(pf[2].y))); \
        lo1.y = pack_bf2(pf[2].z - __bfloat162float(__float2bfloat16(pf[2].z)), \
                         pf[2].w - __bfloat162float(__float2bfloat16(pf[2].w))); \
        lo1.z = pack_bf2(pf[3].x - __bfloat162float(__float2bfloat16(pf[3].x)), \
                         pf[3].y - __bfloat162float(__float2bfloat16(pf[3].y))); \
        lo1.w = pack_bf2(pf[3].z - __bfloat162float(__float2bfloat16(pf[3].z)), \
                         pf[3].w - __bfloat162float(__float2bfloat16(pf[3].w))); \
        asm volatile("st.shared.v4.b32 [%0], {%1,%2,%3,%4};" :: "r"(ab + offH0), \
            "r"(hi0.x), "r"(hi0.y), "r"(hi0.z), "r"(hi0.w) : "memory"); \
        asm volatile("st.shared.v4.b32 [%0], {%1,%2,%3,%4};" :: "r"(ab + offH1), \
            "r"(hi1.x), "r"(hi1.y), "r"(hi1.z), "r"(hi1.w) : "memory"); \
        asm volatile("st.shared.v4.b32 [%0], {%1,%2,%3,%4};" :: "r"(ab + 8192 + offH0), \
            "r"(lo0.x), "r"(lo0.y), "r"(lo0.z), "r"(lo0.w) : "memory"); \
        asm volatile("st.shared.v4.b32 [%0], {%1,%2,%3,%4};" :: "r"(ab + 8192 + offH1), \
            "r"(lo1.x), "r"(lo1.y), "r"(lo1.z), "r"(lo1.w) : "memory"); } while (0)

    #define CPB(kc, st) do { \
        const unsigned char* gsrc = img + (size_t)(nblk * NC + (kc)) * BLK_BYTES + t * 16; \
        uint32_t sdst = sB + (st) * 16384 + t * 16; \
        cp16(sdst,          gsrc); \
        cp16(sdst + 4096,   gsrc + 4096); \
        cp16(sdst + 8192,   gsrc + 8192); \
        cp16(sdst + 12288,  gsrc + 12288); } while (0)

    // ---- prologue: stage 0 ----
    LDA(0);
    CPB(0, 0); CP_COMMIT();
    CVTSTS(0);

    for (int kc = 0; kc < NC; ++kc) {
        const int st = kc & 1;

        // sync1: all warps finished reading stage st^1 (iter kc-1) -> safe to overwrite it
        __syncthreads();
        if (kc + 1 < NC) {
            LDA(kc + 1);
            CPB(kc + 1, st ^ 1); CP_COMMIT();
            CP_WAIT(1);          // stage st B complete; stage st^1 B may be in flight
        } else {
            CP_WAIT(0);
        }
        // sync2: stage st (cp.async B + STS A) visible to all warps
        __syncthreads();

        const uint32_t aBase = sA + st * 16384;
        const uint32_t bBase = sB + st * 16384;
        #pragma unroll
        for (int ks = 0; ks < 2; ++ks) {
            uint32_t ah[2][4], al[2][4];
            #pragma unroll
            for (int mt = 0; mt < 2; ++mt) {
                const int m = wm + mt * 16 + laneMA;
                const int k8 = ks * 2 + laneK8A;
                const uint32_t off = (uint32_t)(m * 64 + ((k8 ^ ((m >> 1) & 3)) << 4));
                ldmx4(ah[mt], aBase + off);
                ldmx4(al[mt], aBase + 8192 + off);
            }
            #pragma unroll
            for (int nt = 0; nt < 4; ++nt) {
                uint32_t bh[4], bl[4];
                const int n = wn + nt * 16 + laneNB;
                const int k8 = ks * 2 + laneK8B;
                const uint32_t off = (uint32_t)(n * 64 + ((k8 ^ ((n >> 1) & 3)) << 4));
                ldmx4(bh, bBase + off);
                ldmx4(bl, bBase + 8192 + off);
                #pragma unroll
                for (int mt = 0; mt < 2; ++mt)
                    #pragma unroll
                    for (int half = 0; half < 2; ++half) {
                        float* a4 = acc[mt][nt * 2 + half];
                        mma_bf16(a4, ah[mt], &bh[half * 2]);
                        mma_bf16(a4, ah[mt], &bl[half * 2]);
                        mma_bf16(a4, al[mt], &bh[half * 2]);
                    }
            }
        }
        // write next A stage; ordered after sync1 of this iter (all kc-1 readers done)
        if (kc + 1 < NC) CVTSTS(st ^ 1);
    }

    // ---- epilogue: accum + bias -> global ----
    const int n0 = nblk * 128;
    #pragma unroll
    for (int mt = 0; mt < 2; ++mt) {
        const int r0 = m0 + wm + mt * 16 + (lane >> 2);
        #pragma unroll
        for (int ng = 0; ng < 8; ++ng) {
            const int c = n0 + wn + ng * 8 + (lane & 3) * 2;
            const float b0 = bias[c], b1 = bias[c + 1];
            float2 v0 = { acc[mt][ng][0] + b0, acc[mt][ng][1] + b1 };
            float2 v1 = { acc[mt][ng][2] + b0, acc[mt][ng][3] + b1 };
            *(float2*)(out + (size_t)r0 * 256 + c)       = v0;
            *(float2*)(out + (size_t)(r0 + 8) * 256 + c) = v1;
        }
    }
    #undef LDA
    #undef CVTSTS
    #undef CPB
}

// ------------------------- attention + softmax + ctx + LayerNorm -------------------------
__global__ void __launch_bounds__(128)
attn_ln(const float* __restrict__ smask, const float* __restrict__ amask,
        const float* __restrict__ wal, const float* __restrict__ bal,
        const float* __restrict__ gamma, const float* __restrict__ beta,
        float* __restrict__ out)
{
    __shared__ float s_e[2 * KQ * D_NEW];
    __shared__ float s_h[2 * D_NEW];
    __shared__ float s_score[2][KQ][HQ];
    __shared__ float s_attn[2][KQ][HQ];
    __shared__ float s_smask[2 * KQ];
    __shared__ float s_amask[2 * KQ];
    __shared__ float s_wal[DKQ];
    __shared__ float s_bal;
    __shared__ float s_red[4][2];
    __shared__ float s_stat[2][2];

    const int t   = threadIdx.x;
    const int g   = t >> 6;
    const int tx  = t & 63;
    const int bn0 = blockIdx.x * 2;

    {
        const float4* es = (const float4*)(g_e + (size_t)bn0 * KQ * 256);
        float4* ed = (float4*)s_e;
        #pragma unroll
        for (int i = 0; i < 12; ++i) ed[t + i * 128] = es[t + i * 128];
        ((float4*)s_h)[t] = ((const float4*)(g_h + (size_t)bn0 * 256))[t];
        if (t < 2 * KQ) {
            s_smask[t] = smask[bn0 * KQ + t];
            s_amask[t] = amask[bn0 * KQ + t];
        }
        if (t < DKQ) s_wal[t] = wal[t];
        if (t == 64) s_bal = bal[0];
    }
    __syncthreads();

    // scores: vectorized float4 LDS (8 iters of 4 lanes each)
    const float bal0 = s_bal;
    for (int idx = t; idx < 2 * KQ * HQ; idx += 128) {
        const int gg  = idx / (KQ * HQ);
        const int rem = idx - gg * (KQ * HQ);
        const int k   = rem >> 3;
        const int hh  = rem & 7;
        const float4* hv = (const float4*)(s_h + gg * 256 + hh * DKQ);
        const float4* ev = (const float4*)(s_e + (gg * KQ + k) * D_NEW + hh * DKQ);
        const float4* wv = (const float4*)s_wal;
        float sc = 0.f;
        #pragma unroll
        for (int i = 0; i < DKQ / 4; ++i) {
            const float4 h4 = hv[i];
            const float4 e4 = ev[i];
            const float4 w4 = wv[i];
            float x;
            x = h4.x + e4.x; x = fmaxf(x, 0.01f * x); sc = fmaf(x, w4.x, sc);
            x = h4.y + e4.y; x = fmaxf(x, 0.01f * x); sc = fmaf(x, w4.y, sc);
            x = h4.z + e4.z; x = fmaxf(x, 0.01f * x); sc = fmaf(x, w4.z, sc);
            x = h4.w + e4.w; x = fmaxf(x, 0.01f * x); sc = fmaf(x, w4.w, sc);
        }
        s_score[gg][k][hh] = sc + bal0 + s_smask[gg * KQ + k];
    }
    __syncthreads();

    if (t < 2 * HQ) {
        const int gg = t >> 3, hh = t & 7;
        float mx = -3.4e38f;
        #pragma unroll
        for (int k = 0; k < KQ; ++k) mx = fmaxf(mx, s_score[gg][k][hh]);
        float ex[KQ], sum = 0.f;
        #pragma unroll
        for (int k = 0; k < KQ; ++k) { ex[k] = __expf(s_score[gg][k][hh] - mx); sum += ex[k]; }
        const float inv = 1.f / sum;
        #pragma unroll
        for (int k = 0; k < KQ; ++k) s_attn[gg][k][hh] = ex[k] * inv * s_amask[gg * KQ + k];
    }
    __syncthreads();

    const int hh = tx >> 3;
    float c0 = 0.f, c1 = 0.f, c2 = 0.f, c3 = 0.f;
    #pragma unroll
    for (int k = 0; k < KQ; ++k) {
        const float a = s_attn[g][k][hh];
        const float4 ev = *(const float4*)(s_e + (g * KQ + k) * D_NEW + tx * 4);
        c0 = fmaf(a, ev.x, c0);
        c1 = fmaf(a, ev.y, c1);
        c2 = fmaf(a, ev.z, c2);
        c3 = fmaf(a, ev.w, c3);
    }
    float v  = c0 + c1 + c2 + c3;
    float v2 = c0 * c0 + c1 * c1 + c2 * c2 + c3 * c3;
    #pragma unroll
    for (int o = 16; o > 0; o >>= 1) {
        v  += __shfl_xor_sync(0xffffffffu, v, o);
        v2 += __shfl_xor_sync(0xffffffffu, v2, o);
    }
    const int warp = t >> 5, lane = t & 31;
    if (lane == 0) { s_red[warp][0] = v; s_red[warp][1] = v2; }
    __syncthreads();
    if (t < 2) {
        const float s  = s_red[2 * t][0] + s_red[2 * t + 1][0];
        const float s2 = s_red[2 * t][1] + s_red[2 * t + 1][1];
        const float mu  = s * (1.f / D_NEW);
        const float var = s2 * (1.f / D_NEW) - mu * mu;
        s_stat[t][0] = mu;
        s_stat[t][1] = rsqrtf(var + LN_EPS);
    }
    __syncthreads();
    const float mu  = s_stat[g][0];
    const float inv = s_stat[g][1];
    const float4 gv = *(const float4*)(gamma + tx * 4);
    const float4 bv = *(const float4*)(beta + tx * 4);
    float4 o;
    o.x = (c0 - mu) * inv * gv.x + bv.x;
    o.y = (c1 - mu) * inv * gv.y + bv.y;
    o.z = (c2 - mu) * inv * gv.z + bv.z;
    o.w = (c3 - mu) * inv * gv.w + bv.w;
    *(float4*)(out + (size_t)(bn0 + g) * D_NEW + tx * 4) = o;
}

// ------------------------- launch -------------------------
#define GEMM_DYN_BYTES 65536

extern "C" void kernel_launch(void* const* d_in, const int* in_sizes, int n_in,
                              void* d_out, int out_size)
{
    (void)in_sizes; (void)n_in; (void)out_size;
    const float* atom   = (const float*)d_in[0];
    const float* nbr    = (const float*)d_in[1];
    const float* smask  = (const float*)d_in[2];
    const float* amask  = (const float*)d_in[3];
    const float* Wa     = (const float*)d_in[4];
    const float* ba     = (const float*)d_in[5];
    const float* Wn     = (const float*)d_in[6];
    const float* bnb    = (const float*)d_in[7];
    const float* wal    = (const float*)d_in[8];
    const float* bal    = (const float*)d_in[9];
    const float* gamma  = (const float*)d_in[10];
    const float* beta   = (const float*)d_in[11];
    float* out = (float*)d_out;

    cudaFuncSetAttribute(gemm_mma, cudaFuncAttributeMaxDynamicSharedMemorySize, GEMM_DYN_BYTES);

    prep_w<<<((D_NBR + D_NEW) * 256 + 255) / 256, 256>>>(Wn, Wa);
    gemm_mma<<<dim3(M_E / 128, 2), 256, GEMM_DYN_BYTES>>>(nbr, bnb, D_NBR, NC_E, 0);
    gemm_mma<<<dim3(BN_TOT / 128, 2), 256, GEMM_DYN_BYTES>>>(atom, ba, D_NEW, NC_H, 1);
    attn_ln<<<BN_TOT / 2, 128>>>(smask, amask, wal, bal, gamma, beta, out);
}

// round 8
// speedup vs baseline: 2.6255x; 1.2324x over previous
#include <cuda_runtime.h>
#include <cuda_bf16.h>
#include <cstdint>

#define KQ     12
#define D_NBR  320
#define D_NEW  256
#define HQ     8
#define DKQ    32
#define LN_EPS 1e-5f
#define BN_TOT (64 * 128)          // 8192 atoms
#define M_E    (BN_TOT * KQ)       // 98304 neighbor rows
#define NC_E   (D_NBR / 32)        // 10 k-chunks (BK=32)
#define NC_H   (D_NEW / 32)        // 8 k-chunks
#define BLK_BYTES 16384            // one (128n x 32k) hi+lo image block (8KB + 8KB)

// ------------------------- device scratch -------------------------
__device__ __align__(16) unsigned char g_WnImg[2 * NC_E * BLK_BYTES];
__device__ __align__(16) unsigned char g_WaImg[2 * NC_H * BLK_BYTES];
__device__ float g_e[(size_t)M_E * 256];
__device__ float g_h[(size_t)BN_TOT * 256];

// ------------------------- helpers -------------------------
__device__ __forceinline__ uint32_t smem_u32(const void* p) {
    uint32_t a;
    asm("{ .reg .u64 t; cvta.to.shared.u64 t, %1; cvt.u32.u64 %0, t; }" : "=r"(a) : "l"(p));
    return a;
}
__device__ __forceinline__ void ldmx4(uint32_t* r, uint32_t addr) {
    asm volatile("ldmatrix.sync.aligned.m8n8.x4.shared.b16 {%0,%1,%2,%3}, [%4];"
        : "=r"(r[0]), "=r"(r[1]), "=r"(r[2]), "=r"(r[3]) : "r"(addr));
}
__device__ __forceinline__ void mma_bf16(float* d, const uint32_t* a, const uint32_t* b) {
    asm volatile(
        "mma.sync.aligned.m16n8k16.row.col.f32.bf16.bf16.f32 "
        "{%0,%1,%2,%3}, {%4,%5,%6,%7}, {%8,%9}, {%0,%1,%2,%3};"
        : "+f"(d[0]), "+f"(d[1]), "+f"(d[2]), "+f"(d[3])
        : "r"(a[0]), "r"(a[1]), "r"(a[2]), "r"(a[3]), "r"(b[0]), "r"(b[1]));
}
__device__ __forceinline__ void cp16(uint32_t saddr, const void* g) {
    asm volatile("cp.async.cg.shared.global [%0], [%1], 16;" :: "r"(saddr), "l"(g) : "memory");
}
#define CP_COMMIT() asm volatile("cp.async.commit_group;" ::: "memory")
#define CP_WAIT(n)  asm volatile("cp.async.wait_group %0;" :: "n"(n) : "memory")

// swizzled offset inside one 128x32 bf16 image (row-major rows of 64B)
__device__ __host__ __forceinline__ uint32_t swz(int r, int k) {
    return (uint32_t)(r * 64 + ((((k >> 3) ^ ((r >> 1) & 3))) << 4) + (k & 7) * 2);
}
__device__ __forceinline__ uint32_t pack_bf2(float a, float b) {
    __nv_bfloat162 p = __floats2bfloat162_rn(a, b);
    return *(uint32_t*)&p;
}

// ------------------------- prep: split W into bf16 hi/lo swizzled images -------------------------
__global__ void prep_w(const float* __restrict__ Wn, const float* __restrict__ Wa) {
    int i = blockIdx.x * blockDim.x + threadIdx.x;
    const float* W; unsigned char* img; int NC, idx;
    if (i < D_NBR * 256)                    { W = Wn; img = g_WnImg; NC = NC_E; idx = i; }
    else if (i < (D_NBR + D_NEW) * 256)     { W = Wa; img = g_WaImg; NC = NC_H; idx = i - D_NBR * 256; }
    else return;
    const int k = idx >> 8, n = idx & 255;
    const int ntile = n >> 7, nl = n & 127, kc = k >> 5, kl = k & 31;
    const float x = W[k * 256 + n];
    const __nv_bfloat16 hi = __float2bfloat16(x);
    const __nv_bfloat16 lo = __float2bfloat16(x - __bfloat162float(hi));
    unsigned char* base = img + (size_t)(ntile * NC + kc) * BLK_BYTES;
    const uint32_t off = swz(nl, kl);
    *(__nv_bfloat16*)(base + off)        = hi;
    *(__nv_bfloat16*)(base + 8192 + off) = lo;
}

// ------------------------- bf16x3 mma GEMM: out[M,256] = X[M,K] @ W[K,256] + bias -----------------
// grid = (M/128, 2); block = 256 (8 warps, warp tile 32m x 64n); BK = 32, double-buffered.
__global__ void __launch_bounds__(256, 2)
gemm_mma(const float* __restrict__ X, const float* __restrict__ bias, int K, int NC, int which)
{
    extern __shared__ unsigned char sm[];
    const unsigned char* img = which ? g_WaImg : g_WnImg;
    float* out = which ? g_h : g_e;

    const int t = threadIdx.x;
    const int lane = t & 31, wid = t >> 5;
    const int m0 = blockIdx.x * 128;
    const int nblk = blockIdx.y;

    const uint32_t sA = smem_u32(sm);          // 2 stages x (hi 8KB + lo 8KB)
    const uint32_t sB = sA + 32768;            // same

    const int wm = (wid & 3) * 32;
    const int wn = (wid >> 2) * 64;

    const int laneMA  = (lane & 7) + ((lane >> 3) & 1) * 8;
    const int laneK8A = lane >> 4;
    const int laneNB  = (lane & 7) + ((lane >> 4) & 1) * 8;
    const int laneK8B = (lane >> 3) & 1;

    float acc[2][8][4];
    #pragma unroll
    for (int mt = 0; mt < 2; ++mt)
        #pragma unroll
        for (int ng = 0; ng < 8; ++ng)
            #pragma unroll
            for (int j = 0; j < 4; ++j) acc[mt][ng][j] = 0.f;

    const int srow = t >> 1, shalf = t & 1;
    const float* Xrow = X + (size_t)(m0 + srow) * K + shalf * 16;
    const uint32_t offH0 = swz(srow, shalf * 16);
    const uint32_t offH1 = swz(srow, shalf * 16 + 8);

    float4 pf[4];
    #define LDA(kc) do { \
        const float4* xp = (const float4*)(Xrow + (kc) * 32); \
        pf[0] = xp[0]; pf[1] = xp[1]; pf[2] = xp[2]; pf[3] = xp[3]; } while (0)

    #define CVTSTS(st) do { \
        uint32_t ab = sA + (st) * 16384; \
        uint4 hi0, lo0, hi1, lo1; \
        hi0.x = pack_bf2(pf[0].x, pf[0].y); hi0.y = pack_bf2(pf[0].z, pf[0].w); \
        hi0.z = pack_bf2(pf[1].x, pf[1].y); hi0.w = pack_bf2(pf[1].z, pf[1].w); \
        hi1.x = pack_bf2(pf[2].x, pf[2].y); hi1.y = pack_bf2(pf[2].z, pf[2].w); \
        hi1.z = pack_bf2(pf[3].x, pf[3].y); hi1.w = pack_bf2(pf[3].z, pf[3].w); \
        lo0.x = pack_bf2(pf[0].x - __bfloat162float(__float2bfloat16(pf[0].x)), \
                         pf[0].y - __bfloat162float(__float2bfloat16(pf[0].y))); \
        lo0.y = pack_bf2(pf[0].z - __bfloat162float(__float2bfloat16(pf[0].z)), \
                         pf[0].w - __bfloat162float(__float2bfloat16(pf[0].w))); \
        lo0.z = pack_bf2(pf[1].x - __bfloat162float(__float2bfloat16(pf[1].x)), \
                         pf[1].y - __bfloat162float(__float2bfloat16(pf[1].y))); \
        lo0.w = pack_bf2(pf[1].z - __bfloat162float(__float2bfloat16(pf[1].z)), \
                         pf[1].w - __bfloat162float(__float2bfloat16(pf[1].w))); \
        lo1.x = pack_bf2(pf[2].x - __bfloat162float(__float2bfloat16(pf[2].x)), \
                         pf[2].y - __bfloat162float(__float2bfloat16(pf[2].y))); \
        lo1.y = pack_bf2(pf[2].z - __bfloat162float(__float2bfloat16(pf[2].z)), \
                         pf[2].w - __bfloat162float(__float2bfloat16(pf[2].w))); \
        lo1.z = pack_bf2(pf[3].x - __bfloat162float(__float2bfloat16(pf[3].x)), \
                         pf[3].y - __bfloat162float(__float2bfloat16(pf[3].y))); \
        lo1.w = pack_bf2(pf[3].z - __bfloat162float(__float2bfloat16(pf[3].z)), \
                         pf[3].w - __bfloat162float(__float2bfloat16(pf[3].w))); \
        asm volatile("st.shared.v4.b32 [%0], {%1,%2,%3,%4};" :: "r"(ab + offH0), \
            "r"(hi0.x), "r"(hi0.y), "r"(hi0.z), "r"(hi0.w) : "memory"); \
        asm volatile("st.shared.v4.b32 [%0], {%1,%2,%3,%4};" :: "r"(ab + offH1), \
            "r"(hi1.x), "r"(hi1.y), "r"(hi1.z), "r"(hi1.w) : "memory"); \
        asm volatile("st.shared.v4.b32 [%0], {%1,%2,%3,%4};" :: "r"(ab + 8192 + offH0), \
            "r"(lo0.x), "r"(lo0.y), "r"(lo0.z), "r"(lo0.w) : "memory"); \
        asm volatile("st.shared.v4.b32 [%0], {%1,%2,%3,%4};" :: "r"(ab + 8192 + offH1), \
            "r"(lo1.x), "r"(lo1.y), "r"(lo1.z), "r"(lo1.w) : "memory"); } while (0)

    #define CPB(kc, st) do { \
        const unsigned char* gsrc = img + (size_t)(nblk * NC + (kc)) * BLK_BYTES + t * 16; \
        uint32_t sdst = sB + (st) * 16384 + t * 16; \
        cp16(sdst,          gsrc); \
        cp16(sdst + 4096,   gsrc + 4096); \
        cp16(sdst + 8192,   gsrc + 8192); \
        cp16(sdst + 12288,  gsrc + 12288); } while (0)

    LDA(0);
    CPB(0, 0); CP_COMMIT();
    CVTSTS(0);

    for (int kc = 0; kc < NC; ++kc) {
        const int st = kc & 1;

        __syncthreads();                  // stage st^1 readers (iter kc-1) done
        if (kc + 1 < NC) {
            LDA(kc + 1);
            CPB(kc + 1, st ^ 1); CP_COMMIT();
            CP_WAIT(1);
        } else {
            CP_WAIT(0);
        }
        __syncthreads();                  // stage st visible

        const uint32_t aBase = sA + st * 16384;
        const uint32_t bBase = sB + st * 16384;
        #pragma unroll
        for (int ks = 0; ks < 2; ++ks) {
            uint32_t ah[2][4], al[2][4];
            #pragma unroll
            for (int mt = 0; mt < 2; ++mt) {
                const int m = wm + mt * 16 + laneMA;
                const int k8 = ks * 2 + laneK8A;
                const uint32_t off = (uint32_t)(m * 64 + ((k8 ^ ((m >> 1) & 3)) << 4));
                ldmx4(ah[mt], aBase + off);
                ldmx4(al[mt], aBase + 8192 + off);
            }
            #pragma unroll
            for (int nt = 0; nt < 4; ++nt) {
                uint32_t bh[4], bl[4];
                const int n = wn + nt * 16 + laneNB;
                const int k8 = ks * 2 + laneK8B;
                const uint32_t off = (uint32_t)(n * 64 + ((k8 ^ ((n >> 1) & 3)) << 4));
                ldmx4(bh, bBase + off);
                ldmx4(bl, bBase + 8192 + off);
                #pragma unroll
                for (int mt = 0; mt < 2; ++mt)
                    #pragma unroll
                    for (int half = 0; half < 2; ++half) {
                        float* a4 = acc[mt][nt * 2 + half];
                        mma_bf16(a4, ah[mt], &bh[half * 2]);
                        mma_bf16(a4, ah[mt], &bl[half * 2]);
                        mma_bf16(a4, al[mt], &bh[half * 2]);
                    }
            }
        }
        if (kc + 1 < NC) CVTSTS(st ^ 1);
    }

    const int n0 = nblk * 128;
    #pragma unroll
    for (int mt = 0; mt < 2; ++mt) {
        const int r0 = m0 + wm + mt * 16 + (lane >> 2);
        #pragma unroll
        for (int ng = 0; ng < 8; ++ng) {
            const int c = n0 + wn + ng * 8 + (lane & 3) * 2;
            const float b0 = bias[c], b1 = bias[c + 1];
            float2 v0 = { acc[mt][ng][0] + b0, acc[mt][ng][1] + b1 };
            float2 v1 = { acc[mt][ng][2] + b0, acc[mt][ng][3] + b1 };
            *(float2*)(out + (size_t)r0 * 256 + c)       = v0;
            *(float2*)(out + (size_t)(r0 + 8) * 256 + c) = v1;
        }
    }
    #undef LDA
    #undef CVTSTS
    #undef CPB
}

// ------------------------- attention + softmax + ctx + LayerNorm (register-resident) ------------
// 256 threads = 4 atoms x 64 threads. Thread owns output cols [4tx, 4tx+4).
// e is loaded once into registers; scores reduced via 8-lane shfl; softmax replicated per-lane.
// Only LayerNorm crosses the warp pair (one smem combine + one syncthreads).
__global__ void __launch_bounds__(256)
attn_ln(const float* __restrict__ smask, const float* __restrict__ amask,
        const float* __restrict__ wal, const float* __restrict__ bal,
        const float* __restrict__ gamma, const float* __restrict__ beta,
        float* __restrict__ out)
{
    __shared__ float s_red[8][2];      // per-warp partial (sum, sumsq)

    const int t    = threadIdx.x;
    const int g    = t >> 6;           // atom in CTA (0..3)
    const int tx   = t & 63;           // column group within atom
    const int warp = t >> 5;
    const int bn   = blockIdx.x * 4 + g;

    // ---- loads (all independent -> high MLP) ----
    const float4 h4 = *(const float4*)(g_h + (size_t)bn * 256 + tx * 4);
    const float4 w4 = *(const float4*)(wal + ((tx * 4) & 31));
    float4 e4[KQ];
    const float* ebase = g_e + (size_t)bn * (KQ * 256) + tx * 4;
    #pragma unroll
    for (int k = 0; k < KQ; ++k) e4[k] = *(const float4*)(ebase + k * 256);
    const float bal0 = __ldg(bal);

    // ---- scores: per-thread 4-col partial, then 8-lane xor reduce ----
    float sc[KQ];
    #pragma unroll
    for (int k = 0; k < KQ; ++k) {
        float x, s = 0.f;
        x = h4.x + e4[k].x; x = fmaxf(x, 0.01f * x); s = fmaf(x, w4.x, s);
        x = h4.y + e4[k].y; x = fmaxf(x, 0.01f * x); s = fmaf(x, w4.y, s);
        x = h4.z + e4[k].z; x = fmaxf(x, 0.01f * x); s = fmaf(x, w4.z, s);
        x = h4.w + e4[k].w; x = fmaxf(x, 0.01f * x); s = fmaf(x, w4.w, s);
        sc[k] = s;
    }
    #pragma unroll
    for (int o = 1; o < 8; o <<= 1)
        #pragma unroll
        for (int k = 0; k < KQ; ++k)
            sc[k] += __shfl_xor_sync(0xffffffffu, sc[k], o);

    // ---- mask + softmax over K, in registers (replicated across the 8 lanes) ----
    float mx = -3.4e38f;
    #pragma unroll
    for (int k = 0; k < KQ; ++k) {
        sc[k] += bal0 + __ldg(smask + bn * KQ + k);
        mx = fmaxf(mx, sc[k]);
    }
    float sum = 0.f;
    #pragma unroll
    for (int k = 0; k < KQ; ++k) { sc[k] = __expf(sc[k] - mx); sum += sc[k]; }
    const float inv = 1.f / sum;
    #pragma unroll
    for (int k = 0; k < KQ; ++k) sc[k] = sc[k] * inv * __ldg(amask + bn * KQ + k);

    // ---- ctx from the same registers ----
    float c0 = 0.f, c1 = 0.f, c2 = 0.f, c3 = 0.f;
    #pragma unroll
    for (int k = 0; k < KQ; ++k) {
        c0 = fmaf(sc[k], e4[k].x, c0);
        c1 = fmaf(sc[k], e4[k].y, c1);
        c2 = fmaf(sc[k], e4[k].z, c2);
        c3 = fmaf(sc[k], e4[k].w, c3);
    }

    // ---- LayerNorm over 256 cols = 64 threads x 4 ----
    float v  = c0 + c1 + c2 + c3;
    float v2 = c0 * c0 + c1 * c1 + c2 * c2 + c3 * c3;
    #pragma unroll
    for (int o = 16; o > 0; o >>= 1) {
        v  += __shfl_xor_sync(0xffffffffu, v, o);
        v2 += __shfl_xor_sync(0xffffffffu, v2, o);
    }
    if ((t & 31) == 0) { s_red[warp][0] = v; s_red[warp][1] = v2; }
    __syncthreads();
    const float s  = s_red[g * 2][0] + s_red[g * 2 + 1][0];
    const float s2 = s_red[g * 2][1] + s_red[g * 2 + 1][1];
    const float mu  = s * (1.f / D_NEW);
    const float var = s2 * (1.f / D_NEW) - mu * mu;
    const float rinv = rsqrtf(var + LN_EPS);

    const float4 gv = *(const float4*)(gamma + tx * 4);
    const float4 bv = *(const float4*)(beta + tx * 4);
    float4 o;
    o.x = (c0 - mu) * rinv * gv.x + bv.x;
    o.y = (c1 - mu) * rinv * gv.y + bv.y;
    o.z = (c2 - mu) * rinv * gv.z + bv.z;
    o.w = (c3 - mu) * rinv * gv.w + bv.w;
    *(float4*)(out + (size_t)bn * D_NEW + tx * 4) = o;
}

// ------------------------- launch -------------------------
#define GEMM_DYN_BYTES 65536

extern "C" void kernel_launch(void* const* d_in, const int* in_sizes, int n_in,
                              void* d_out, int out_size)
{
    (void)in_sizes; (void)n_in; (void)out_size;
    const float* atom   = (const float*)d_in[0];
    const float* nbr    = (const float*)d_in[1];
    const float* smask  = (const float*)d_in[2];
    const float* amask  = (const float*)d_in[3];
    const float* Wa     = (const float*)d_in[4];
    const float* ba     = (const float*)d_in[5];
    const float* Wn     = (const float*)d_in[6];
    const float* bnb    = (const float*)d_in[7];
    const float* wal    = (const float*)d_in[8];
    const float* bal    = (const float*)d_in[9];
    const float* gamma  = (const float*)d_in[10];
    const float* beta   = (const float*)d_in[11];
    float* out = (float*)d_out;

    cudaFuncSetAttribute(gemm_mma, cudaFuncAttributeMaxDynamicSharedMemorySize, GEMM_DYN_BYTES);

    prep_w<<<((D_NBR + D_NEW) * 256 + 255) / 256, 256>>>(Wn, Wa);
    gemm_mma<<<dim3(M_E / 128, 2), 256, GEMM_DYN_BYTES>>>(nbr, bnb, D_NBR, NC_E, 0);
    gemm_mma<<<dim3(BN_TOT / 128, 2), 256, GEMM_DYN_BYTES>>>(atom, ba, D_NEW, NC_H, 1);
    attn_ln<<<BN_TOT / 4, 256>>>(smask, amask, wal, bal, gamma, beta, out);
}

// round 9
// speedup vs baseline: 2.7103x; 1.0323x over previous
#include <cuda_runtime.h>
#include <cuda_bf16.h>
#include <cstdint>

#define KQ     12
#define D_NBR  320
#define D_NEW  256
#define HQ     8
#define DKQ    32
#define LN_EPS 1e-5f
#define BN_TOT (64 * 128)          // 8192 atoms
#define M_E    (BN_TOT * KQ)       // 98304 neighbor rows
#define NC_E   (D_NBR / 32)        // 10 k-chunks (BK=32)
#define NC_H   (D_NEW / 32)        // 8 k-chunks
#define BLK_BYTES 16384            // Wa: one (128n x 32k) hi+lo image block
#define WNC_BYTES 32768            // Wn: one (256n x 32k) hi+lo image block

// ------------------------- device scratch -------------------------
__device__ __align__(16) unsigned char g_WnImg[NC_E * WNC_BYTES];          // 320 KB
__device__ __align__(16) unsigned char g_WaImg[2 * NC_H * BLK_BYTES];      // 256 KB
__device__ float g_h[(size_t)BN_TOT * 256];

// ------------------------- helpers -------------------------
__device__ __forceinline__ uint32_t smem_u32(const void* p) {
    uint32_t a;
    asm("{ .reg .u64 t; cvta.to.shared.u64 t, %1; cvt.u32.u64 %0, t; }" : "=r"(a) : "l"(p));
    return a;
}
__device__ __forceinline__ void ldmx4(uint32_t* r, uint32_t addr) {
    asm volatile("ldmatrix.sync.aligned.m8n8.x4.shared.b16 {%0,%1,%2,%3}, [%4];"
        : "=r"(r[0]), "=r"(r[1]), "=r"(r[2]), "=r"(r[3]) : "r"(addr));
}
__device__ __forceinline__ void mma_bf16(float* d, const uint32_t* a, const uint32_t* b) {
    asm volatile(
        "mma.sync.aligned.m16n8k16.row.col.f32.bf16.bf16.f32 "
        "{%0,%1,%2,%3}, {%4,%5,%6,%7}, {%8,%9}, {%0,%1,%2,%3};"
        : "+f"(d[0]), "+f"(d[1]), "+f"(d[2]), "+f"(d[3])
        : "r"(a[0]), "r"(a[1]), "r"(a[2]), "r"(a[3]), "r"(b[0]), "r"(b[1]));
}
__device__ __forceinline__ void cp16(uint32_t saddr, const void* g) {
    asm volatile("cp.async.cg.shared.global [%0], [%1], 16;" :: "r"(saddr), "l"(g) : "memory");
}
#define CP_COMMIT() asm volatile("cp.async.commit_group;" ::: "memory")
#define CP_WAIT(n)  asm volatile("cp.async.wait_group %0;" :: "n"(n) : "memory")

// swizzled offset inside an (R rows x 32k) bf16 image (row-major rows of 64B)
__device__ __host__ __forceinline__ uint32_t swz(int r, int k) {
    return (uint32_t)(r * 64 + ((((k >> 3) ^ ((r >> 1) & 3))) << 4) + (k & 7) * 2);
}
__device__ __forceinline__ uint32_t pack_bf2(float a, float b) {
    __nv_bfloat162 p = __floats2bfloat162_rn(a, b);
    return *(uint32_t*)&p;
}

// ------------------------- prep: split W into bf16 hi/lo swizzled images -------------------------
__global__ void prep_w(const float* __restrict__ Wn, const float* __restrict__ Wa) {
    int i = blockIdx.x * blockDim.x + threadIdx.x;
    if (i < D_NBR * 256) {
        // Wn: full-width image, [kc] -> (256n x 32k) hi + lo
        const int k = i >> 8, n = i & 255;
        const int kc = k >> 5, kl = k & 31;
        const float x = Wn[k * 256 + n];
        const __nv_bfloat16 hi = __float2bfloat16(x);
        const __nv_bfloat16 lo = __float2bfloat16(x - __bfloat162float(hi));
        unsigned char* base = g_WnImg + (size_t)kc * WNC_BYTES;
        const uint32_t off = swz(n, kl);
        *(__nv_bfloat16*)(base + off)         = hi;
        *(__nv_bfloat16*)(base + 16384 + off) = lo;
    } else if (i < (D_NBR + D_NEW) * 256) {
        // Wa: old layout, [ntile][kc] -> (128n x 32k) hi + lo
        const int idx = i - D_NBR * 256;
        const int k = idx >> 8, n = idx & 255;
        const int ntile = n >> 7, nl = n & 127, kc = k >> 5, kl = k & 31;
        const float x = Wa[k * 256 + n];
        const __nv_bfloat16 hi = __float2bfloat16(x);
        const __nv_bfloat16 lo = __float2bfloat16(x - __bfloat162float(hi));
        unsigned char* base = g_WaImg + (size_t)(ntile * NC_H + kc) * BLK_BYTES;
        const uint32_t off = swz(nl, kl);
        *(__nv_bfloat16*)(base + off)        = hi;
        *(__nv_bfloat16*)(base + 8192 + off) = lo;
    }
}

// ------------------------- h-GEMM (bf16x3 mma): g_h = atom @ Wa + ba -------------------------
__global__ void __launch_bounds__(256, 2)
gemm_h(const float* __restrict__ X, const float* __restrict__ bias)
{
    extern __shared__ unsigned char sm[];
    const int t = threadIdx.x;
    const int lane = t & 31, wid = t >> 5;
    const int m0 = blockIdx.x * 128;
    const int nblk = blockIdx.y;
    const int K = D_NEW, NC = NC_H;

    const uint32_t sA = smem_u32(sm);
    const uint32_t sB = sA + 32768;

    const int wm = (wid & 3) * 32;
    const int wn = (wid >> 2) * 64;
    const int laneMA  = (lane & 7) + ((lane >> 3) & 1) * 8;
    const int laneK8A = lane >> 4;
    const int laneNB  = (lane & 7) + ((lane >> 4) & 1) * 8;
    const int laneK8B = (lane >> 3) & 1;

    float acc[2][8][4];
    #pragma unroll
    for (int mt = 0; mt < 2; ++mt)
        #pragma unroll
        for (int ng = 0; ng < 8; ++ng)
            #pragma unroll
            for (int j = 0; j < 4; ++j) acc[mt][ng][j] = 0.f;

    const int srow = t >> 1, shalf = t & 1;
    const float* Xrow = X + (size_t)(m0 + srow) * K + shalf * 16;
    const uint32_t offH0 = swz(srow, shalf * 16);
    const uint32_t offH1 = swz(srow, shalf * 16 + 8);

    float4 pf[4];
    #define LDA(kc) do { \
        const float4* xp = (const float4*)(Xrow + (kc) * 32); \
        pf[0] = xp[0]; pf[1] = xp[1]; pf[2] = xp[2]; pf[3] = xp[3]; } while (0)

    #define CVTSTS(st, abase, lodelta) do { \
        uint32_t ab = (abase); \
        uint4 hi0, lo0, hi1, lo1; \
        hi0.x = pack_bf2(pf[0].x, pf[0].y); hi0.y = pack_bf2(pf[0].z, pf[0].w); \
        hi0.z = pack_bf2(pf[1].x, pf[1].y); hi0.w = pack_bf2(pf[1].z, pf[1].w); \
        hi1.x = pack_bf2(pf[2].x, pf[2].y); hi1.y = pack_bf2(pf[2].z, pf[2].w); \
        hi1.z = pack_bf2(pf[3].x, pf[3].y); hi1.w = pack_bf2(pf[3].z, pf[3].w); \
        lo0.x = pack_bf2(pf[0].x - __bfloat162float(__float2bfloat16(pf[0].x)), \
                         pf[0].y - __bfloat162float(__float2bfloat16(pf[0].y))); \
        lo0.y = pack_bf2(pf[0].z - __bfloat162float(__float2bfloat16(pf[0].z)), \
                         pf[0].w - __bfloat162float(__float2bfloat16(pf[0].w))); \
        lo0.z = pack_bf2(pf[1].x - __bfloat162float(__float2bfloat16(pf[1].x)), \
                         pf[1].y - __bfloat162float(__float2bfloat16(pf[1].y))); \
        lo0.w = pack_bf2(pf[1].z - __bfloat162float(__float2bfloat16(pf[1].z)), \
                         pf[1].w - __bfloat162float(__float2bfloat16(pf[1].w))); \
        lo1.x = pack_bf2(pf[2].x - __bfloat162float(__float2bfloat16(pf[2].x)), \
                         pf[2].y - __bfloat162float(__float2bfloat16(pf[2].y))); \
        lo1.y = pack_bf2(pf[2].z - __bfloat162float(__float2bfloat16(pf[2].z)), \
                         pf[2].w - __bfloat162float(__float2bfloat16(pf[2].w))); \
        lo1.z = pack_bf2(pf[3].x - __bfloat162float(__float2bfloat16(pf[3].x)), \
                         pf[3].y - __bfloat162float(__float2bfloat16(pf[3].y))); \
        lo1.w = pack_bf2(pf[3].z - __bfloat162float(__float2bfloat16(pf[3].z)), \
                         pf[3].w - __bfloat162float(__float2bfloat16(pf[3].w))); \
        asm volatile("st.shared.v4.b32 [%0], {%1,%2,%3,%4};" :: "r"(ab + offH0), \
            "r"(hi0.x), "r"(hi0.y), "r"(hi0.z), "r"(hi0.w) : "memory"); \
        asm volatile("st.shared.v4.b32 [%0], {%1,%2,%3,%4};" :: "r"(ab + offH1), \
            "r"(hi1.x), "r"(hi1.y), "r"(hi1.z), "r"(hi1.w) : "memory"); \
        asm volatile("st.shared.v4.b32 [%0], {%1,%2,%3,%4};" :: "r"(ab + (lodelta) + offH0), \
            "r"(lo0.x), "r"(lo0.y), "r"(lo0.z), "r"(lo0.w) : "memory"); \
        asm volatile("st.shared.v4.b32 [%0], {%1,%2,%3,%4};" :: "r"(ab + (lodelta) + offH1), \
            "r"(lo1.x), "r"(lo1.y), "r"(lo1.z), "r"(lo1.w) : "memory"); } while (0)

    #define CPB(kc, st) do { \
        const unsigned char* gsrc = g_WaImg + (size_t)((nblk * NC + (kc))) * BLK_BYTES + t * 16; \
        uint32_t sdst = sB + (st) * 16384 + t * 16; \
        cp16(sdst,          gsrc); \
        cp16(sdst + 4096,   gsrc + 4096); \
        cp16(sdst + 8192,   gsrc + 8192); \
        cp16(sdst + 12288,  gsrc + 12288); } while (0)

    LDA(0);
    CPB(0, 0); CP_COMMIT();
    CVTSTS(0, sA, 8192);

    for (int kc = 0; kc < NC; ++kc) {
        const int st = kc & 1;
        __syncthreads();
        if (kc + 1 < NC) {
            LDA(kc + 1);
            CPB(kc + 1, st ^ 1); CP_COMMIT();
            CP_WAIT(1);
        } else {
            CP_WAIT(0);
        }
        __syncthreads();

        const uint32_t aBase = sA + st * 16384;
        const uint32_t bBase = sB + st * 16384;
        #pragma unroll
        for (int ks = 0; ks < 2; ++ks) {
            uint32_t ah[2][4], al[2][4];
            #pragma unroll
            for (int mt = 0; mt < 2; ++mt) {
                const int m = wm + mt * 16 + laneMA;
                const int k8 = ks * 2 + laneK8A;
                const uint32_t off = (uint32_t)(m * 64 + ((k8 ^ ((m >> 1) & 3)) << 4));
                ldmx4(ah[mt], aBase + off);
                ldmx4(al[mt], aBase + 8192 + off);
            }
            #pragma unroll
            for (int nt = 0; nt < 4; ++nt) {
                uint32_t bh[4], bl[4];
                const int n = wn + nt * 16 + laneNB;
                const int k8 = ks * 2 + laneK8B;
                const uint32_t off = (uint32_t)(n * 64 + ((k8 ^ ((n >> 1) & 3)) << 4));
                ldmx4(bh, bBase + off);
                ldmx4(bl, bBase + 8192 + off);
                #pragma unroll
                for (int mt = 0; mt < 2; ++mt)
                    #pragma unroll
                    for (int half = 0; half < 2; ++half) {
                        float* a4 = acc[mt][nt * 2 + half];
                        mma_bf16(a4, ah[mt], &bh[half * 2]);
                        mma_bf16(a4, ah[mt], &bl[half * 2]);
                        mma_bf16(a4, al[mt], &bh[half * 2]);
                    }
            }
        }
        if (kc + 1 < NC) CVTSTS(st ^ 1, sA + (st ^ 1) * 16384, 8192);
    }

    const int n0 = nblk * 128;
    #pragma unroll
    for (int mt = 0; mt < 2; ++mt) {
        const int r0 = m0 + wm + mt * 16 + (lane >> 2);
        #pragma unroll
        for (int ng = 0; ng < 8; ++ng) {
            const int c = n0 + wn + ng * 8 + (lane & 3) * 2;
            const float b0 = bias[c], b1 = bias[c + 1];
            float2 v0 = { acc[mt][ng][0] + b0, acc[mt][ng][1] + b1 };
            float2 v1 = { acc[mt][ng][2] + b0, acc[mt][ng][3] + b1 };
            *(float2*)(g_h + (size_t)r0 * 256 + c)       = v0;
            *(float2*)(g_h + (size_t)(r0 + 8) * 256 + c) = v1;
        }
    }
}

// ------------------------- fused e-GEMM + attention + LayerNorm -------------------------
// CTA: M=96 rows (8 atoms), N=256 full width, 512 threads (16 warps, warp tile 48x32).
// e never touches DRAM: acc -> smem -> attention -> out.
#define FM 96
#define ESTR 260                    // s_e row stride in floats (bank-staggered)
#define FDYN_BYTES (FM * ESTR * 4 + 1024)   // >= staging (24576 + 65536 = 90112)? no: take max below

__global__ void __launch_bounds__(512, 1)
fused_e_attn(const float* __restrict__ nbr, const float* __restrict__ bnb,
             const float* __restrict__ smask, const float* __restrict__ amask,
             const float* __restrict__ wal, const float* __restrict__ bal,
             const float* __restrict__ gamma, const float* __restrict__ beta,
             float* __restrict__ out)
{
    extern __shared__ unsigned char sm[];
    __shared__ float s_red[16][2];

    const int t = threadIdx.x;
    const int lane = t & 31, wid = t >> 5;
    const int m0 = blockIdx.x * FM;

    const uint32_t sA = smem_u32(sm);            // A: 2 stages x (hi 6KB + lo 6KB) = 24KB
    const uint32_t sB = sA + 24576;              // B: 2 stages x (hi 16KB + lo 16KB) = 64KB
    float* s_e = (float*)sm;                     // epilogue overlay: 96 x 260 fp32

    const int wm = (wid & 1) * 48;               // 2 m-warps
    const int wn = (wid >> 1) * 32;              // 8 n-warps
    const int laneMA  = (lane & 7) + ((lane >> 3) & 1) * 8;
    const int laneK8A = lane >> 4;
    const int laneNB  = (lane & 7) + ((lane >> 4) & 1) * 8;
    const int laneK8B = (lane >> 3) & 1;

    float acc[3][4][4];
    #pragma unroll
    for (int mt = 0; mt < 3; ++mt)
        #pragma unroll
        for (int ng = 0; ng < 4; ++ng)
            #pragma unroll
            for (int j = 0; j < 4; ++j) acc[mt][ng][j] = 0.f;

    // A staging: threads t<192, 2 per row
    const int srow = t >> 1, shalf = t & 1;
    const bool stager = (t < 2 * FM);
    const float* Xrow = nbr + (size_t)(m0 + srow) * D_NBR + shalf * 16;
    const uint32_t offH0 = swz(srow, shalf * 16);
    const uint32_t offH1 = swz(srow, shalf * 16 + 8);

    float4 pf[4];
    #define FLDA(kc) do { if (stager) { \
        const float4* xp = (const float4*)(Xrow + (kc) * 32); \
        pf[0] = xp[0]; pf[1] = xp[1]; pf[2] = xp[2]; pf[3] = xp[3]; } } while (0)

    #define FCVTSTS(st) do { if (stager) { \
        uint32_t ab = sA + (st) * 12288; \
        uint4 hi0, lo0, hi1, lo1; \
        hi0.x = pack_bf2(pf[0].x, pf[0].y); hi0.y = pack_bf2(pf[0].z, pf[0].w); \
        hi0.z = pack_bf2(pf[1].x, pf[1].y); hi0.w = pack_bf2(pf[1].z, pf[1].w); \
        hi1.x = pack_bf2(pf[2].x, pf[2].y); hi1.y = pack_bf2(pf[2].z, pf[2].w); \
        hi1.z = pack_bf2(pf[3].x, pf[3].y); hi1.w = pack_bf2(pf[3].z, pf[3].w); \
        lo0.x = pack_bf2(pf[0].x - __bfloat162float(__float2bfloat16(pf[0].x)), \
                         pf[0].y - __bfloat162float(__float2bfloat16(pf[0].y))); \
        lo0.y = pack_bf2(pf[0].z - __bfloat162float(__float2bfloat16(pf[0].z)), \
                         pf[0].w - __bfloat162float(__float2bfloat16(pf[0].w))); \
        lo0.z = pack_bf2(pf[1].x - __bfloat162float(__float2bfloat16(pf[1].x)), \
                         pf[1].y - __bfloat162float(__float2bfloat16(pf[1].y))); \
        lo0.w = pack_bf2(pf[1].z - __bfloat162float(__float2bfloat16(pf[1].z)), \
                         pf[1].w - __bfloat162float(__float2bfloat16(pf[1].w))); \
        lo1.x = pack_bf2(pf[2].x - __bfloat162float(__float2bfloat16(pf[2].x)), \
                         pf[2].y - __bfloat162float(__float2bfloat16(pf[2].y))); \
        lo1.y = pack_bf2(pf[2].z - __bfloat162float(__float2bfloat16(pf[2].z)), \
                         pf[2].w - __bfloat162float(__float2bfloat16(pf[2].w))); \
        lo1.z = pack_bf2(pf[3].x - __bfloat162float(__float2bfloat16(pf[3].x)), \
                         pf[3].y - __bfloat162float(__float2bfloat16(pf[3].y))); \
        lo1.w = pack_bf2(pf[3].z - __bfloat162float(__float2bfloat16(pf[3].z)), \
                         pf[3].w - __bfloat162float(__float2bfloat16(pf[3].w))); \
        asm volatile("st.shared.v4.b32 [%0], {%1,%2,%3,%4};" :: "r"(ab + offH0), \
            "r"(hi0.x), "r"(hi0.y), "r"(hi0.z), "r"(hi0.w) : "memory"); \
        asm volatile("st.shared.v4.b32 [%0], {%1,%2,%3,%4};" :: "r"(ab + offH1), \
            "r"(hi1.x), "r"(hi1.y), "r"(hi1.z), "r"(hi1.w) : "memory"); \
        asm volatile("st.shared.v4.b32 [%0], {%1,%2,%3,%4};" :: "r"(ab + 6144 + offH0), \
            "r"(lo0.x), "r"(lo0.y), "r"(lo0.z), "r"(lo0.w) : "memory"); \
        asm volatile("st.shared.v4.b32 [%0], {%1,%2,%3,%4};" :: "r"(ab + 6144 + offH1), \
            "r"(lo1.x), "r"(lo1.y), "r"(lo1.z), "r"(lo1.w) : "memory"); } } while (0)

    #define FCPB(kc, st) do { \
        const unsigned char* gsrc = g_WnImg + (size_t)(kc) * WNC_BYTES + t * 16; \
        uint32_t sdst = sB + (st) * 32768 + t * 16; \
        cp16(sdst,           gsrc); \
        cp16(sdst + 8192,    gsrc + 8192); \
        cp16(sdst + 16384,   gsrc + 16384); \
        cp16(sdst + 24576,   gsrc + 24576); } while (0)

    FLDA(0);
    FCPB(0, 0); CP_COMMIT();
    FCVTSTS(0);

    for (int kc = 0; kc < NC_E; ++kc) {
        const int st = kc & 1;
        __syncthreads();                  // stage st^1 readers done
        if (kc + 1 < NC_E) {
            FLDA(kc + 1);
            FCPB(kc + 1, st ^ 1); CP_COMMIT();
            CP_WAIT(1);
        } else {
            CP_WAIT(0);
        }
        __syncthreads();                  // stage st visible

        const uint32_t aBase = sA + st * 12288;
        const uint32_t bBase = sB + st * 32768;
        #pragma unroll
        for (int ks = 0; ks < 2; ++ks) {
            uint32_t ah[3][4], al[3][4];
            #pragma unroll
            for (int mt = 0; mt < 3; ++mt) {
                const int m = wm + mt * 16 + laneMA;
                const int k8 = ks * 2 + laneK8A;
                const uint32_t off = (uint32_t)(m * 64 + ((k8 ^ ((m >> 1) & 3)) << 4));
                ldmx4(ah[mt], aBase + off);
                ldmx4(al[mt], aBase + 6144 + off);
            }
            #pragma unroll
            for (int nt = 0; nt < 2; ++nt) {
                uint32_t bh[4], bl[4];
                const int n = wn + nt * 16 + laneNB;
                const int k8 = ks * 2 + laneK8B;
                const uint32_t off = (uint32_t)(n * 64 + ((k8 ^ ((n >> 1) & 3)) << 4));
                ldmx4(bh, bBase + off);
                ldmx4(bl, bBase + 16384 + off);
                #pragma unroll
                for (int mt = 0; mt < 3; ++mt)
                    #pragma unroll
                    for (int half = 0; half < 2; ++half) {
                        float* a4 = acc[mt][nt * 2 + half];
                        mma_bf16(a4, ah[mt], &bh[half * 2]);
                        mma_bf16(a4, ah[mt], &bl[half * 2]);
                        mma_bf16(a4, al[mt], &bh[half * 2]);
                    }
            }
        }
        if (kc + 1 < NC_E) FCVTSTS(st ^ 1);
    }

    // ---- epilogue 1: acc + bias -> smem e tile ----
    __syncthreads();                      // all ldmatrix reads done; s_e overlays stages
    #pragma unroll
    for (int mt = 0; mt < 3; ++mt) {
        const int r0 = wm + mt * 16 + (lane >> 2);
        #pragma unroll
        for (int ng = 0; ng < 4; ++ng) {
            const int c = wn + ng * 8 + (lane & 3) * 2;
            const float b0 = __ldg(bnb + c), b1 = __ldg(bnb + c + 1);
            float2 v0 = { acc[mt][ng][0] + b0, acc[mt][ng][1] + b1 };
            float2 v1 = { acc[mt][ng][2] + b0, acc[mt][ng][3] + b1 };
            *(float2*)(s_e + (size_t)r0 * ESTR + c)       = v0;
            *(float2*)(s_e + (size_t)(r0 + 8) * ESTR + c) = v1;
        }
    }
    __syncthreads();

    // ---- epilogue 2: attention + softmax + ctx + LayerNorm (8 atoms x 64 threads) ----
    {
        const int g  = t >> 6;            // atom in CTA (0..7)
        const int tx = t & 63;
        const int bn = blockIdx.x * 8 + g;

        const float4 h4 = *(const float4*)(g_h + (size_t)bn * 256 + tx * 4);
        const float4 w4 = *(const float4*)(wal + ((tx * 4) & 31));
        float4 e4[KQ];
        #pragma unroll
        for (int k = 0; k < KQ; ++k)
            e4[k] = *(const float4*)(s_e + (size_t)(g * KQ + k) * ESTR + tx * 4);
        const float bal0 = __ldg(bal);

        float sc[KQ];
        #pragma unroll
        for (int k = 0; k < KQ; ++k) {
            float x, s = 0.f;
            x = h4.x + e4[k].x; x = fmaxf(x, 0.01f * x); s = fmaf(x, w4.x, s);
            x = h4.y + e4[k].y; x = fmaxf(x, 0.01f * x); s = fmaf(x, w4.y, s);
            x = h4.z + e4[k].z; x = fmaxf(x, 0.01f * x); s = fmaf(x, w4.z, s);
            x = h4.w + e4[k].w; x = fmaxf(x, 0.01f * x); s = fmaf(x, w4.w, s);
            sc[k] = s;
        }
        #pragma unroll
        for (int o = 1; o < 8; o <<= 1)
            #pragma unroll
            for (int k = 0; k < KQ; ++k)
                sc[k] += __shfl_xor_sync(0xffffffffu, sc[k], o);

        float mx = -3.4e38f;
        #pragma unroll
        for (int k = 0; k < KQ; ++k) {
            sc[k] += bal0 + __ldg(smask + bn * KQ + k);
            mx = fmaxf(mx, sc[k]);
        }
        float sum = 0.f;
        #pragma unroll
        for (int k = 0; k < KQ; ++k) { sc[k] = __expf(sc[k] - mx); sum += sc[k]; }
        const float inv = 1.f / sum;
        #pragma unroll
        for (int k = 0; k < KQ; ++k) sc[k] = sc[k] * inv * __ldg(amask + bn * KQ + k);

        float c0 = 0.f, c1 = 0.f, c2 = 0.f, c3 = 0.f;
        #pragma unroll
        for (int k = 0; k < KQ; ++k) {
            c0 = fmaf(sc[k], e4[k].x, c0);
            c1 = fmaf(sc[k], e4[k].y, c1);
            c2 = fmaf(sc[k], e4[k].z, c2);
            c3 = fmaf(sc[k], e4[k].w, c3);
        }

        float v  = c0 + c1 + c2 + c3;
        float v2 = c0 * c0 + c1 * c1 + c2 * c2 + c3 * c3;
        #pragma unroll
        for (int o = 16; o > 0; o >>= 1) {
            v  += __shfl_xor_sync(0xffffffffu, v, o);
            v2 += __shfl_xor_sync(0xffffffffu, v2, o);
        }
        if ((t & 31) == 0) { s_red[wid][0] = v; s_red[wid][1] = v2; }
        __syncthreads();
        const float s  = s_red[g * 2][0] + s_red[g * 2 + 1][0];
        const float s2 = s_red[g * 2][1] + s_red[g * 2 + 1][1];
        const float mu  = s * (1.f / D_NEW);
        const float var = s2 * (1.f / D_NEW) - mu * mu;
        const float rinv = rsqrtf(var + LN_EPS);

        const float4 gv = *(const float4*)(gamma + tx * 4);
        const float4 bv = *(const float4*)(beta + tx * 4);
        float4 o;
        o.x = (c0 - mu) * rinv * gv.x + bv.x;
        o.y = (c1 - mu) * rinv * gv.y + bv.y;
        o.z = (c2 - mu) * rinv * gv.z + bv.z;
        o.w = (c3 - mu) * rinv * gv.w + bv.w;
        *(float4*)(out + (size_t)bn * D_NEW + tx * 4) = o;
    }
    #undef FLDA
    #undef FCVTSTS
    #undef FCPB
}

// ------------------------- launch -------------------------
#define GEMM_DYN_BYTES 65536
#define FUSED_DYN_BYTES (FM * ESTR * 4 > 90112 ? FM * ESTR * 4 : 90112)   // max(99840, 90112)

extern "C" void kernel_launch(void* const* d_in, const int* in_sizes, int n_in,
                              void* d_out, int out_size)
{
    (void)in_sizes; (void)n_in; (void)out_size;
    const float* atom   = (const float*)d_in[0];
    const float* nbr    = (const float*)d_in[1];
    const float* smask  = (const float*)d_in[2];
    const float* amask  = (const float*)d_in[3];
    const float* Wa     = (const float*)d_in[4];
    const float* ba     = (const float*)d_in[5];
    const float* Wn     = (const float*)d_in[6];
    const float* bnb    = (const float*)d_in[7];
    const float* wal    = (const float*)d_in[8];
    const float* bal    = (const float*)d_in[9];
    const float* gamma  = (const float*)d_in[10];
    const float* beta   = (const float*)d_in[11];
    float* out = (float*)d_out;

    cudaFuncSetAttribute(gemm_h, cudaFuncAttributeMaxDynamicSharedMemorySize, GEMM_DYN_BYTES);
    cudaFuncSetAttribute(fused_e_attn, cudaFuncAttributeMaxDynamicSharedMemorySize, FUSED_DYN_BYTES);

    prep_w<<<((D_NBR + D_NEW) * 256 + 255) / 256, 256>>>(Wn, Wa);
    gemm_h<<<dim3(BN_TOT / 128, 2), 256, GEMM_DYN_BYTES>>>(atom, ba);
    fused_e_attn<<<M_E / FM, 512, FUSED_DYN_BYTES>>>(nbr, bnb, smask, amask,
                                                     wal, bal, gamma, beta, out);
}